// round 3
// baseline (speedup 1.0000x reference)
#include <cuda_runtime.h>

#define BB   4
#define NQ   196
#define NK   196
#define DMOD 512
#define NH   8
#define DK   64
#define MROWS (BB*NQ)   // 784
#define KPAD 65
#define TQ   16

__device__ float g_qsig[BB*NQ*DMOD];
__device__ float g_kp[BB*NQ*DMOD];
__device__ float g_vp[BB*NQ*DMOD];
__device__ float g_img[BB*NQ*DMOD];

__device__ __forceinline__ float tanhap(float x) {
    float y; asm("tanh.approx.f32 %0, %1;" : "=f"(y) : "f"(x)); return y;
}

// ---------------------------------------------------------------------------
// GEMM: Y = X @ W^T + b.  BM=128, BN=64, BK=16, 256 threads, 8x4 micro-tile.
// EPI=0: plain + bias (projections). EPI=1: out-projection + sigmoid gate.
// ---------------------------------------------------------------------------
template<int EPI>
__global__ void __launch_bounds__(256) gemm_kernel(
    const float* __restrict__ X, const float* __restrict__ W,
    const float* __restrict__ bias, float* __restrict__ Y)
{
    __shared__ float As[16][128];   // [k][m] transposed
    __shared__ float Bs[16][64];    // [k][n] transposed

    const int tid = threadIdx.x;
    const int tx  = tid & 15;       // 0..15 -> 4 cols each
    const int ty  = tid >> 4;       // 0..15 -> 4+4 rows each
    const int gm_base = blockIdx.y * 128;
    const int gn_base = blockIdx.x * 64;

    // global-load mapping
    const int ar  = tid >> 1;            // 0..127
    const int ac4 = (tid & 1) * 8;       // 0 or 8
    const int br  = tid >> 2;            // 0..63
    const int bc4 = (tid & 3) * 4;       // 0,4,8,12

    float acc[2][4][4];
#pragma unroll
    for (int h = 0; h < 2; h++)
#pragma unroll
        for (int i = 0; i < 4; i++)
#pragma unroll
            for (int j = 0; j < 4; j++) acc[h][i][j] = 0.f;

    const float4* As4 = (const float4*)&As[0][0];
    const float4* Bs4 = (const float4*)&Bs[0][0];

    for (int kt = 0; kt < DMOD; kt += 16) {
        int gm = gm_base + ar;
        float4 x0 = make_float4(0.f,0.f,0.f,0.f), x1 = x0;
        if (gm < MROWS) {
            x0 = *(const float4*)(X + (long)gm * DMOD + kt + ac4);
            x1 = *(const float4*)(X + (long)gm * DMOD + kt + ac4 + 4);
        }
        As[ac4+0][ar]=x0.x; As[ac4+1][ar]=x0.y; As[ac4+2][ar]=x0.z; As[ac4+3][ar]=x0.w;
        As[ac4+4][ar]=x1.x; As[ac4+5][ar]=x1.y; As[ac4+6][ar]=x1.z; As[ac4+7][ar]=x1.w;

        float4 wv = *(const float4*)(W + (long)(gn_base + br) * DMOD + kt + bc4);
        Bs[bc4+0][br]=wv.x; Bs[bc4+1][br]=wv.y; Bs[bc4+2][br]=wv.z; Bs[bc4+3][br]=wv.w;
        __syncthreads();

#pragma unroll
        for (int kk = 0; kk < 16; kk++) {
            float4 a0 = As4[kk*32 + ty];
            float4 a1 = As4[kk*32 + 16 + ty];
            float4 bv = Bs4[kk*16 + tx];
            float a0a[4] = {a0.x,a0.y,a0.z,a0.w};
            float a1a[4] = {a1.x,a1.y,a1.z,a1.w};
            float bb[4]  = {bv.x,bv.y,bv.z,bv.w};
#pragma unroll
            for (int i = 0; i < 4; i++)
#pragma unroll
                for (int j = 0; j < 4; j++) {
                    acc[0][i][j] += a0a[i]*bb[j];
                    acc[1][i][j] += a1a[i]*bb[j];
                }
        }
        __syncthreads();
    }

#pragma unroll
    for (int h = 0; h < 2; h++)
#pragma unroll
        for (int i = 0; i < 4; i++) {
            int m = gm_base + h*64 + ty*4 + i;
            if (m >= MROWS) continue;
#pragma unroll
            for (int j = 0; j < 4; j++) {
                int n = gn_base + tx*4 + j;
                float o = acc[h][i][j] + bias[n];
                if (EPI == 0) {
                    Y[(long)m * DMOD + n] = o;
                } else {
                    float qs = g_qsig[(long)m * DMOD + n];
                    // sigmoid(qs*o)*o  via tanh
                    float s = 0.5f + 0.5f * tanhap(0.5f * qs * o);
                    Y[(long)m * DMOD + n] = s * o;
                }
            }
        }
}

// ---------------------------------------------------------------------------
// Attention core. Grid: (13, B*H=32). 128 threads = 4 warps.
// Each warp handles 2 query-pairs (4 q total) per block tile of 16 q.
// Pairing shares every K/V smem load across 2 queries.
// ---------------------------------------------------------------------------
__global__ void __launch_bounds__(128) attn_kernel(const float* __restrict__ scale)
{
    extern __shared__ float sm[];
    float* Ksh  = sm;                        // NK*KPAD  (12740)
    float* Vsh  = Ksh + NK * KPAD;           // NK*64    (12544)
    float* pbuf = Vsh + NK * 64;             // 4*2*NK   (1568)  holds 0.5*p
    float* qsm  = pbuf + 4 * 2 * NK;         // 4*2*64   (512)

    const int bh   = blockIdx.y;
    const int b    = bh >> 3;
    const int h    = bh & 7;
    const int tid  = threadIdx.x;
    const int w    = tid >> 5;
    const int lane = tid & 31;

    const float* kbase = g_kp + (long)(b * NQ) * DMOD + h * DK;
    const float* vbase = g_vp + (long)(b * NQ) * DMOD + h * DK;

    for (int idx = tid; idx < NK * 16; idx += 128) {
        int n  = idx >> 4;
        int c4 = (idx & 15) << 2;
        float4 kv = *(const float4*)(kbase + (long)n * DMOD + c4);
        Ksh[n * KPAD + c4 + 0] = kv.x; Ksh[n * KPAD + c4 + 1] = kv.y;
        Ksh[n * KPAD + c4 + 2] = kv.z; Ksh[n * KPAD + c4 + 3] = kv.w;
        float4 vv = *(const float4*)(vbase + (long)n * DMOD + c4);
        *(float4*)(Vsh + n * 64 + c4) = vv;
    }
    __syncthreads();

    const int q0base = blockIdx.x * TQ;
    float* pbA = pbuf + (w * 2 + 0) * NK;
    float* pbB = pbuf + (w * 2 + 1) * NK;
    float* qsA = qsm + (w * 2 + 0) * 64;
    float* qsB = qsm + (w * 2 + 1) * 64;

    for (int jj = 0; jj < 2; jj++) {
        int pi = w + 4 * jj;            // pair index 0..7
        int qa = q0base + 2 * pi;
        int qb = qa + 1;
        if (qa >= NQ) break;            // pairs are fully valid or fully invalid

        const float* qrowA = g_qsig + (long)(b * NQ + qa) * DMOD + h * DK;
        const float* qrowB = g_qsig + (long)(b * NQ + qb) * DMOD + h * DK;
        float qa0 = qrowA[lane], qa1 = qrowA[lane + 32];
        float qb0 = qrowB[lane], qb1 = qrowB[lane + 32];
        qsA[lane] = qa0; qsA[lane + 32] = qa1;
        qsB[lane] = qb0; qsB[lane + 32] = qb1;
        // halved q for tanh-sigmoid
        float qha0 = 0.5f*qa0, qha1 = 0.5f*qa1, qhb0 = 0.5f*qb0, qhb1 = 0.5f*qb1;
        __syncwarp();

        // ---- Pass 1: scores for both queries. Lane owns k = lane + 32*i. ----
        float sa[7], sb[7];
        int kb[7];
#pragma unroll
        for (int i = 0; i < 7; i++) { sa[i]=0.f; sb[i]=0.f; kb[i]=(i*32+lane)*KPAD; }
#pragma unroll 4
        for (int d = 0; d < 64; d++) {
            float qda = qsA[d];
            float qdb = qsB[d];
#pragma unroll
            for (int i = 0; i < 7; i++) {
                float kv = Ksh[kb[i] + d];   // OOB rows land in Vsh: defined, masked
                sa[i] += qda * kv;
                sb[i] += qdb * kv;
            }
        }

        const float* scrA = scale + (long)(h * NQ + qa) * NK;
        const float* scrB = scale + (long)(h * NQ + qb) * NK;
        float mxa = -1e30f, mxb = -1e30f;
#pragma unroll
        for (int i = 0; i < 7; i++) {
            int k = i * 32 + lane;
            if (k < NK) {
                sa[i] *= scrA[k]; mxa = fmaxf(mxa, sa[i]);
                sb[i] *= scrB[k]; mxb = fmaxf(mxb, sb[i]);
            }
        }
#pragma unroll
        for (int o = 16; o; o >>= 1) {
            mxa = fmaxf(mxa, __shfl_xor_sync(0xffffffffu, mxa, o));
            mxb = fmaxf(mxb, __shfl_xor_sync(0xffffffffu, mxb, o));
        }

        float suma = 0.f, sumb = 0.f;
#pragma unroll
        for (int i = 0; i < 7; i++) {
            int k = i * 32 + lane;
            if (k < NK) {
                float pa = __expf(sa[i] - mxa);
                float pb = __expf(sb[i] - mxb);
                pbA[k] = 0.5f * pa;
                pbB[k] = 0.5f * pb;
                suma += pa; sumb += pb;
            }
        }
#pragma unroll
        for (int o = 16; o; o >>= 1) {
            suma += __shfl_xor_sync(0xffffffffu, suma, o);
            sumb += __shfl_xor_sync(0xffffffffu, sumb, o);
        }
        float rdena = __fdividef(1.f, suma);
        float rdenb = __fdividef(1.f, sumb);
        __syncwarp();

        // ---- Pass 2: gated accumulation. Lane owns d = lane, lane+32. ----
        // p*sigmoid(e) = hp + hp*tanh(0.5*e), hp = 0.5*p (prefolded in pbuf)
        float aa0 = 0.f, aa1 = 0.f, ab0 = 0.f, ab1 = 0.f;
#pragma unroll 4
        for (int k = 0; k < NK; k++) {
            float hpa = pbA[k];
            float hpb = pbB[k];
            float k0 = Ksh[k * KPAD + lane];
            float k1 = Ksh[k * KPAD + lane + 32];
            float v0 = Vsh[k * 64 + lane];
            float v1 = Vsh[k * 64 + lane + 32];
            float t;
            t = tanhap(qha0 * k0); aa0 = fmaf(fmaf(hpa, t, hpa), v0, aa0);
            t = tanhap(qha1 * k1); aa1 = fmaf(fmaf(hpa, t, hpa), v1, aa1);
            t = tanhap(qhb0 * k0); ab0 = fmaf(fmaf(hpb, t, hpb), v0, ab0);
            t = tanhap(qhb1 * k1); ab1 = fmaf(fmaf(hpb, t, hpb), v1, ab1);
        }

        float* orA = g_img + (long)(b * NQ + qa) * DMOD + h * DK;
        float* orB = g_img + (long)(b * NQ + qb) * DMOD + h * DK;
        orA[lane]      = aa0 * rdena;
        orA[lane + 32] = aa1 * rdena;
        orB[lane]      = ab0 * rdenb;
        orB[lane + 32] = ab1 * rdenb;
        __syncwarp();
    }
}

// ---------------------------------------------------------------------------
extern "C" void kernel_launch(void* const* d_in, const int* in_sizes, int n_in,
                              void* d_out, int out_size)
{
    const float* queries = (const float*)d_in[0];
    const float* keys    = (const float*)d_in[1];
    const float* values  = (const float*)d_in[2];
    const float* Wq      = (const float*)d_in[3];
    const float* bq      = (const float*)d_in[4];
    const float* Wk      = (const float*)d_in[5];
    const float* bk      = (const float*)d_in[6];
    const float* Wv      = (const float*)d_in[7];
    const float* bv      = (const float*)d_in[8];
    const float* Wo      = (const float*)d_in[9];
    const float* bo      = (const float*)d_in[10];
    const float* scale   = (const float*)d_in[11];
    float* out = (float*)d_out;

    float* qsig; cudaGetSymbolAddress((void**)&qsig, g_qsig);
    float* kp;   cudaGetSymbolAddress((void**)&kp,   g_kp);
    float* vp;   cudaGetSymbolAddress((void**)&vp,   g_vp);
    float* img;  cudaGetSymbolAddress((void**)&img,  g_img);

    const int smem_attn = (NK * KPAD + NK * 64 + 4 * 2 * NK + 4 * 2 * 64) * (int)sizeof(float);
    cudaFuncSetAttribute(attn_kernel, cudaFuncAttributeMaxDynamicSharedMemorySize, smem_attn);

    dim3 gg(DMOD / 64, (MROWS + 127) / 128);
    gemm_kernel<0><<<gg, 256>>>(queries, Wq, bq, qsig);
    gemm_kernel<0><<<gg, 256>>>(keys,    Wk, bk, kp);
    gemm_kernel<0><<<gg, 256>>>(values,  Wv, bv, vp);

    dim3 g2((NQ + TQ - 1) / TQ, BB * NH);
    attn_kernel<<<g2, 128, smem_attn>>>(scale);

    gemm_kernel<1><<<gg, 256>>>(img, Wo, bo, out);
}

// round 6
// speedup vs baseline: 1.1142x; 1.1142x over previous
#include <cuda_runtime.h>
#include <cuda_fp16.h>

#define BB   4
#define NQ   196
#define NK   196
#define DMOD 512
#define NH   8
#define DK   64
#define MROWS (BB*NQ)   // 784
#define KPAD 65

__device__ float g_qsig[BB*NQ*DMOD];
__device__ float g_kp[BB*NQ*DMOD];
__device__ float g_vp[BB*NQ*DMOD];
__device__ float g_img[BB*NQ*DMOD];

__device__ __forceinline__ float tanhap(float x) {
    float y; asm("tanh.approx.f32 %0, %1;" : "=f"(y) : "f"(x)); return y;
}

// ---------------------------------------------------------------------------
// GEMM: Y = X @ W^T + b.  BM=64, BN=64, BK=32, 128 threads, 8x4 micro-tile.
// blockIdx.z selects input set (fused Q/K/V projections). EPI=1: gate epilogue.
// smem traffic: 48B per 32 FMA = 1.5 B/FMA -> FMA-pipe bound (<=2.0 budget).
// ---------------------------------------------------------------------------
template<int EPI>
__global__ void __launch_bounds__(128) gemm_kernel(
    const float* __restrict__ X0, const float* __restrict__ X1, const float* __restrict__ X2,
    const float* __restrict__ W0, const float* __restrict__ W1, const float* __restrict__ W2,
    const float* __restrict__ b0, const float* __restrict__ b1, const float* __restrict__ b2,
    float* __restrict__ Y0, float* __restrict__ Y1, float* __restrict__ Y2)
{
    const float* X; const float* W; const float* bias; float* Y;
    if (blockIdx.z == 0)      { X = X0; W = W0; bias = b0; Y = Y0; }
    else if (blockIdx.z == 1) { X = X1; W = W1; bias = b1; Y = Y1; }
    else                      { X = X2; W = W2; bias = b2; Y = Y2; }

    __shared__ float As[32][64];   // [k][m]
    __shared__ float Bs[32][64];   // [k][n]

    const int tid = threadIdx.x;
    const int tx  = tid & 15;       // 4 cols
    const int ty  = tid >> 4;       // 0..7 -> rows ty*4 and 32+ty*4
    const int gm_base = blockIdx.y * 64;
    const int gn_base = blockIdx.x * 64;

    const int lr = tid >> 1;             // 0..63
    const int lc = (tid & 1) * 16;       // 0 or 16

    float acc[2][4][4];
#pragma unroll
    for (int h = 0; h < 2; h++)
#pragma unroll
        for (int i = 0; i < 4; i++)
#pragma unroll
            for (int j = 0; j < 4; j++) acc[h][i][j] = 0.f;

    const float4* As4 = (const float4*)&As[0][0];
    const float4* Bs4 = (const float4*)&Bs[0][0];

    // prologue: load tile 0 into registers
    float4 xa[4], wb[4];
    {
        int gm = gm_base + lr;
        const float* xp = X + (long)gm * DMOD + lc;
        bool mv = (gm < MROWS);
#pragma unroll
        for (int j = 0; j < 4; j++)
            xa[j] = mv ? *(const float4*)(xp + 4*j) : make_float4(0.f,0.f,0.f,0.f);
        const float* wp = W + (long)(gn_base + lr) * DMOD + lc;
#pragma unroll
        for (int j = 0; j < 4; j++)
            wb[j] = *(const float4*)(wp + 4*j);
    }

    for (int t = 0; t < DMOD / 32; t++) {
        // store staged regs to smem
#pragma unroll
        for (int j = 0; j < 4; j++) {
            As[lc + 4*j + 0][lr] = xa[j].x; As[lc + 4*j + 1][lr] = xa[j].y;
            As[lc + 4*j + 2][lr] = xa[j].z; As[lc + 4*j + 3][lr] = xa[j].w;
            Bs[lc + 4*j + 0][lr] = wb[j].x; Bs[lc + 4*j + 1][lr] = wb[j].y;
            Bs[lc + 4*j + 2][lr] = wb[j].z; Bs[lc + 4*j + 3][lr] = wb[j].w;
        }
        __syncthreads();

        // prefetch next tile (overlaps with compute below)
        if (t + 1 < DMOD / 32) {
            int kt = (t + 1) * 32;
            int gm = gm_base + lr;
            const float* xp = X + (long)gm * DMOD + kt + lc;
            bool mv = (gm < MROWS);
#pragma unroll
            for (int j = 0; j < 4; j++)
                xa[j] = mv ? *(const float4*)(xp + 4*j) : make_float4(0.f,0.f,0.f,0.f);
            const float* wp = W + (long)(gn_base + lr) * DMOD + kt + lc;
#pragma unroll
            for (int j = 0; j < 4; j++)
                wb[j] = *(const float4*)(wp + 4*j);
        }

#pragma unroll
        for (int kk = 0; kk < 32; kk++) {
            float4 a0 = As4[kk*16 + ty];
            float4 a1 = As4[kk*16 + 8 + ty];
            float4 bv = Bs4[kk*16 + tx];
            float a0a[4] = {a0.x,a0.y,a0.z,a0.w};
            float a1a[4] = {a1.x,a1.y,a1.z,a1.w};
            float bb[4]  = {bv.x,bv.y,bv.z,bv.w};
#pragma unroll
            for (int i = 0; i < 4; i++)
#pragma unroll
                for (int j = 0; j < 4; j++) {
                    acc[0][i][j] += a0a[i]*bb[j];
                    acc[1][i][j] += a1a[i]*bb[j];
                }
        }
        __syncthreads();
    }

#pragma unroll
    for (int h = 0; h < 2; h++)
#pragma unroll
        for (int i = 0; i < 4; i++) {
            int m = gm_base + h*32 + ty*4 + i;
            if (m >= MROWS) continue;
#pragma unroll
            for (int j = 0; j < 4; j++) {
                int n = gn_base + tx*4 + j;
                float o = acc[h][i][j] + bias[n];
                if (EPI == 0) {
                    Y[(long)m * DMOD + n] = o;
                } else {
                    float qs = g_qsig[(long)m * DMOD + n];
                    float s = 0.5f + 0.5f * tanhap(0.5f * qs * o);
                    Y[(long)m * DMOD + n] = s * o;
                }
            }
        }
}

// ---------------------------------------------------------------------------
// Attention core. Grid: (13, 32). 256 threads = 8 warps; each warp owns one
// query PAIR (2 consecutive q). smem ~105KB -> 2 blocks/SM (16 warps) to
// saturate the MUFU pipe (tanh gating is the floor: ~17us chip-wide).
// ---------------------------------------------------------------------------
__global__ void __launch_bounds__(256) attn_kernel(const float* __restrict__ scale)
{
    extern __shared__ float sm[];
    float*  Ksh   = sm;                        // NK*KPAD
    float*  Vsh   = Ksh + NK * KPAD;           // NK*64
    __half* pbufh = (__half*)(Vsh + NK * 64);  // 16*NK halves (0.5*p)

    const int bh   = blockIdx.y;
    const int b    = bh >> 3;
    const int h    = bh & 7;
    const int tid  = threadIdx.x;
    const int w    = tid >> 5;
    const int lane = tid & 31;

    const float* kbase = g_kp + (long)(b * NQ) * DMOD + h * DK;
    const float* vbase = g_vp + (long)(b * NQ) * DMOD + h * DK;

    for (int idx = tid; idx < NK * 16; idx += 256) {
        int n  = idx >> 4;
        int c4 = (idx & 15) << 2;
        float4 kv = *(const float4*)(kbase + (long)n * DMOD + c4);
        Ksh[n * KPAD + c4 + 0] = kv.x; Ksh[n * KPAD + c4 + 1] = kv.y;
        Ksh[n * KPAD + c4 + 2] = kv.z; Ksh[n * KPAD + c4 + 3] = kv.w;
        float4 vv = *(const float4*)(vbase + (long)n * DMOD + c4);
        *(float4*)(Vsh + n * 64 + c4) = vv;
    }
    __syncthreads();

    const int qa = blockIdx.x * 16 + 2 * w;
    const int qb = qa + 1;
    if (qa < NQ) {
        __half* pbA = pbufh + (w * 2 + 0) * NK;
        __half* pbB = pbufh + (w * 2 + 1) * NK;

        const float* qrowA = g_qsig + (long)(b * NQ + qa) * DMOD + h * DK;
        const float* qrowB = g_qsig + (long)(b * NQ + qb) * DMOD + h * DK;
        float qa0 = qrowA[lane], qa1 = qrowA[lane + 32];
        float qb0 = qrowB[lane], qb1 = qrowB[lane + 32];
        float qha0 = 0.5f*qa0, qha1 = 0.5f*qa1, qhb0 = 0.5f*qb0, qhb1 = 0.5f*qb1;

        // ---- Pass 1: scores. Lane owns k = lane + 32*i (7 slots). ----
        float sa[7], sb[7];
        int kb[7];
#pragma unroll
        for (int i = 0; i < 7; i++) { sa[i]=0.f; sb[i]=0.f; kb[i]=(i*32+lane)*KPAD; }
        // q broadcast via shuffle (no smem): d<32 uses qa0/qb0, d>=32 uses qa1/qb1
#pragma unroll 4
        for (int d = 0; d < 32; d++) {
            float qda = __shfl_sync(0xffffffffu, qa0, d);
            float qdb = __shfl_sync(0xffffffffu, qb0, d);
#pragma unroll
            for (int i = 0; i < 7; i++) {
                float kv = Ksh[kb[i] + d];   // OOB rows land in Vsh: defined, masked
                sa[i] += qda * kv;
                sb[i] += qdb * kv;
            }
        }
#pragma unroll 4
        for (int d = 0; d < 32; d++) {
            float qda = __shfl_sync(0xffffffffu, qa1, d);
            float qdb = __shfl_sync(0xffffffffu, qb1, d);
#pragma unroll
            for (int i = 0; i < 7; i++) {
                float kv = Ksh[kb[i] + 32 + d];
                sa[i] += qda * kv;
                sb[i] += qdb * kv;
            }
        }

        const float* scrA = scale + (long)(h * NQ + qa) * NK;
        const float* scrB = scale + (long)(h * NQ + qb) * NK;
        float mxa = -1e30f, mxb = -1e30f;
#pragma unroll
        for (int i = 0; i < 7; i++) {
            int k = i * 32 + lane;
            if (k < NK) {
                sa[i] *= scrA[k]; mxa = fmaxf(mxa, sa[i]);
                sb[i] *= scrB[k]; mxb = fmaxf(mxb, sb[i]);
            }
        }
#pragma unroll
        for (int o = 16; o; o >>= 1) {
            mxa = fmaxf(mxa, __shfl_xor_sync(0xffffffffu, mxa, o));
            mxb = fmaxf(mxb, __shfl_xor_sync(0xffffffffu, mxb, o));
        }

        float suma = 0.f, sumb = 0.f;
#pragma unroll
        for (int i = 0; i < 7; i++) {
            int k = i * 32 + lane;
            if (k < NK) {
                float pa = __expf(sa[i] - mxa);
                float pb = __expf(sb[i] - mxb);
                pbA[k] = __float2half(0.5f * pa);
                pbB[k] = __float2half(0.5f * pb);
                suma += pa; sumb += pb;
            }
        }
#pragma unroll
        for (int o = 16; o; o >>= 1) {
            suma += __shfl_xor_sync(0xffffffffu, suma, o);
            sumb += __shfl_xor_sync(0xffffffffu, sumb, o);
        }
        float rdena = __fdividef(1.f, suma);
        float rdenb = __fdividef(1.f, sumb);
        __syncwarp();

        // ---- Pass 2: gated accumulation. Lane owns d = lane, lane+32. ----
        // p*sigmoid(e) = hp + hp*tanh(0.5*e), hp = 0.5*p (prefolded)
        float aa0 = 0.f, aa1 = 0.f, ab0 = 0.f, ab1 = 0.f;
#pragma unroll 4
        for (int k = 0; k < NK; k++) {
            float hpa = __half2float(pbA[k]);
            float hpb = __half2float(pbB[k]);
            float k0 = Ksh[k * KPAD + lane];
            float k1 = Ksh[k * KPAD + lane + 32];
            float v0 = Vsh[k * 64 + lane];
            float v1 = Vsh[k * 64 + lane + 32];
            float t;
            t = tanhap(qha0 * k0); aa0 = fmaf(fmaf(hpa, t, hpa), v0, aa0);
            t = tanhap(qha1 * k1); aa1 = fmaf(fmaf(hpa, t, hpa), v1, aa1);
            t = tanhap(qhb0 * k0); ab0 = fmaf(fmaf(hpb, t, hpb), v0, ab0);
            t = tanhap(qhb1 * k1); ab1 = fmaf(fmaf(hpb, t, hpb), v1, ab1);
        }

        float* orA = g_img + (long)(b * NQ + qa) * DMOD + h * DK;
        float* orB = g_img + (long)(b * NQ + qb) * DMOD + h * DK;
        orA[lane]      = aa0 * rdena;
        orA[lane + 32] = aa1 * rdena;
        orB[lane]      = ab0 * rdenb;
        orB[lane + 32] = ab1 * rdenb;
    }
}

// ---------------------------------------------------------------------------
extern "C" void kernel_launch(void* const* d_in, const int* in_sizes, int n_in,
                              void* d_out, int out_size)
{
    const float* queries = (const float*)d_in[0];
    const float* keys    = (const float*)d_in[1];
    const float* values  = (const float*)d_in[2];
    const float* Wq      = (const float*)d_in[3];
    const float* bq      = (const float*)d_in[4];
    const float* Wk      = (const float*)d_in[5];
    const float* bk      = (const float*)d_in[6];
    const float* Wv      = (const float*)d_in[7];
    const float* bv      = (const float*)d_in[8];
    const float* Wo      = (const float*)d_in[9];
    const float* bo      = (const float*)d_in[10];
    const float* scale   = (const float*)d_in[11];
    float* out = (float*)d_out;

    float* qsig; cudaGetSymbolAddress((void**)&qsig, g_qsig);
    float* kp;   cudaGetSymbolAddress((void**)&kp,   g_kp);
    float* vp;   cudaGetSymbolAddress((void**)&vp,   g_vp);
    float* img;  cudaGetSymbolAddress((void**)&img,  g_img);

    const int smem_attn = (NK * KPAD + NK * 64) * (int)sizeof(float)
                        + 16 * NK * (int)sizeof(__half);
    cudaFuncSetAttribute(attn_kernel, cudaFuncAttributeMaxDynamicSharedMemorySize, smem_attn);

    // Fused Q/K/V projections: grid (8, 13, 3) = 312 blocks of 128 threads
    dim3 gg(DMOD / 64, (MROWS + 63) / 64, 3);
    gemm_kernel<0><<<gg, 128>>>(queries, keys, values,
                                Wq, Wk, Wv, bq, bk, bv,
                                qsig, kp, vp);

    dim3 g2((NQ + 15) / 16, BB * NH);
    attn_kernel<<<g2, 256, smem_attn>>>(scale);

    dim3 g3(DMOD / 64, (MROWS + 63) / 64, 1);
    gemm_kernel<1><<<g3, 128>>>(img, img, img,
                                Wo, Wo, Wo, bo, bo, bo,
                                out, out, out);
}

// round 8
// speedup vs baseline: 1.8343x; 1.6463x over previous
#include <cuda_runtime.h>
#include <cuda_fp16.h>

#define BB   4
#define NQ   196
#define NK   196
#define DMOD 512
#define NH   8
#define DK   64
#define MROWS (BB*NQ)   // 784
#define KPAD 65
#define SPAD 68         // smem k-tile row pad (floats): 16B-aligned, 2-way STS

__device__ float g_qsig[BB*NQ*DMOD];
__device__ float g_kp[BB*NQ*DMOD];
__device__ float g_vp[BB*NQ*DMOD];
__device__ float g_img[BB*NQ*DMOD];

__device__ __forceinline__ float tanhap(float x) {
    float y; asm("tanh.approx.f32 %0, %1;" : "=f"(y) : "f"(x)); return y;
}

// ---------------------------------------------------------------------------
// GEMM: Y = X @ W^T + b.  BM=64, BN=64, BK=32, 256 threads, 4x4 micro-tile.
// Grid: (N-tiles=8, matrices, M-tiles=13) -- M slowest so the light M-tail
// (16 rows) lands in the last wave. 16.8 warps/SM at 2.1 blocks/SM.
// Inner loop: a-load is a 2-address broadcast, b-load conflict-free ->
// crossbar ~4cyc per warp-kk vs 8 FMA-cyc -> FMA-pipe bound.
// ---------------------------------------------------------------------------
template<int EPI>
__global__ void __launch_bounds__(256) gemm_kernel(
    const float* __restrict__ X0, const float* __restrict__ X1, const float* __restrict__ X2,
    const float* __restrict__ W0, const float* __restrict__ W1, const float* __restrict__ W2,
    const float* __restrict__ b0, const float* __restrict__ b1, const float* __restrict__ b2,
    float* __restrict__ Y0, float* __restrict__ Y1, float* __restrict__ Y2)
{
    const float* X; const float* W; const float* bias; float* Y;
    if (blockIdx.y == 0)      { X = X0; W = W0; bias = b0; Y = Y0; }
    else if (blockIdx.y == 1) { X = X1; W = W1; bias = b1; Y = Y1; }
    else                      { X = X2; W = W2; bias = b2; Y = Y2; }

    __shared__ float As[32][SPAD];   // [k][m]
    __shared__ float Bs[32][SPAD];   // [k][n]

    const int tid = threadIdx.x;
    const int tx  = tid & 15;        // cols tx*4..+3
    const int ty  = tid >> 4;        // rows ty*4..+3
    const int gm_base = blockIdx.z * 64;
    const int gn_base = blockIdx.x * 64;

    // global loads: 64 rows x 8 float4-cols = 512 float4, 2 per thread
    const int lr  = tid >> 2;        // 0..63
    const int f4c = tid & 3;         // float4 col 0..3 (and +4)

    float acc[4][4];
#pragma unroll
    for (int i = 0; i < 4; i++)
#pragma unroll
        for (int j = 0; j < 4; j++) acc[i][j] = 0.f;

    const float4* As4 = (const float4*)&As[0][0];
    const float4* Bs4 = (const float4*)&Bs[0][0];

    float4 xa0, xa1, wb0, wb1;
    {
        int gm = gm_base + lr;
        bool mv = (gm < MROWS);
        const float* xp = X + (long)gm * DMOD + f4c * 4;
        xa0 = mv ? *(const float4*)(xp)      : make_float4(0.f,0.f,0.f,0.f);
        xa1 = mv ? *(const float4*)(xp + 16) : make_float4(0.f,0.f,0.f,0.f);
        const float* wp = W + (long)(gn_base + lr) * DMOD + f4c * 4;
        wb0 = *(const float4*)(wp);
        wb1 = *(const float4*)(wp + 16);
    }

    for (int t = 0; t < DMOD / 32; t++) {
        // transposed scatter into [k][m] (2-way STS with SPAD=68)
        int c0 = f4c * 4;
        As[c0 + 0][lr] = xa0.x; As[c0 + 1][lr] = xa0.y; As[c0 + 2][lr] = xa0.z; As[c0 + 3][lr] = xa0.w;
        As[c0 +16][lr] = xa1.x; As[c0 +17][lr] = xa1.y; As[c0 +18][lr] = xa1.z; As[c0 +19][lr] = xa1.w;
        Bs[c0 + 0][lr] = wb0.x; Bs[c0 + 1][lr] = wb0.y; Bs[c0 + 2][lr] = wb0.z; Bs[c0 + 3][lr] = wb0.w;
        Bs[c0 +16][lr] = wb1.x; Bs[c0 +17][lr] = wb1.y; Bs[c0 +18][lr] = wb1.z; Bs[c0 +19][lr] = wb1.w;
        __syncthreads();

        if (t + 1 < DMOD / 32) {
            int kt = (t + 1) * 32;
            int gm = gm_base + lr;
            bool mv = (gm < MROWS);
            const float* xp = X + (long)gm * DMOD + kt + f4c * 4;
            xa0 = mv ? *(const float4*)(xp)      : make_float4(0.f,0.f,0.f,0.f);
            xa1 = mv ? *(const float4*)(xp + 16) : make_float4(0.f,0.f,0.f,0.f);
            const float* wp = W + (long)(gn_base + lr) * DMOD + kt + f4c * 4;
            wb0 = *(const float4*)(wp);
            wb1 = *(const float4*)(wp + 16);
        }

#pragma unroll
        for (int kk = 0; kk < 32; kk++) {
            float4 av = As4[kk * (SPAD/4) + ty];   // 2-addr broadcast in warp
            float4 bv = Bs4[kk * (SPAD/4) + tx];   // 16 distinct, conflict-free
            float aa[4] = {av.x, av.y, av.z, av.w};
            float bb[4] = {bv.x, bv.y, bv.z, bv.w};
#pragma unroll
            for (int i = 0; i < 4; i++)
#pragma unroll
                for (int j = 0; j < 4; j++)
                    acc[i][j] = fmaf(aa[i], bb[j], acc[i][j]);
        }
        __syncthreads();
    }

    // epilogue: float4 stores
    const int n0 = gn_base + tx * 4;
    float4 bv4 = *(const float4*)(bias + n0);
#pragma unroll
    for (int i = 0; i < 4; i++) {
        int m = gm_base + ty * 4 + i;
        if (m >= MROWS) continue;
        float o0 = acc[i][0] + bv4.x;
        float o1 = acc[i][1] + bv4.y;
        float o2 = acc[i][2] + bv4.z;
        float o3 = acc[i][3] + bv4.w;
        if (EPI == 1) {
            float4 qs = *(const float4*)(g_qsig + (long)m * DMOD + n0);
            o0 *= 0.5f + 0.5f * tanhap(0.5f * qs.x * o0);
            o1 *= 0.5f + 0.5f * tanhap(0.5f * qs.y * o1);
            o2 *= 0.5f + 0.5f * tanhap(0.5f * qs.z * o2);
            o3 *= 0.5f + 0.5f * tanhap(0.5f * qs.w * o3);
        }
        *(float4*)(Y + (long)m * DMOD + n0) = make_float4(o0, o1, o2, o3);
    }
}

// ---------------------------------------------------------------------------
// Attention core (unchanged from R6 pass). Grid (13, 32), 256 threads;
// each warp owns one query pair; ~105KB smem -> 2 blocks/SM.
// ---------------------------------------------------------------------------
__global__ void __launch_bounds__(256) attn_kernel(const float* __restrict__ scale)
{
    extern __shared__ float sm[];
    float*  Ksh   = sm;                        // NK*KPAD
    float*  Vsh   = Ksh + NK * KPAD;           // NK*64
    __half* pbufh = (__half*)(Vsh + NK * 64);  // 16*NK halves (0.5*p)

    const int bh   = blockIdx.y;
    const int b    = bh >> 3;
    const int h    = bh & 7;
    const int tid  = threadIdx.x;
    const int w    = tid >> 5;
    const int lane = tid & 31;

    const float* kbase = g_kp + (long)(b * NQ) * DMOD + h * DK;
    const float* vbase = g_vp + (long)(b * NQ) * DMOD + h * DK;

    for (int idx = tid; idx < NK * 16; idx += 256) {
        int n  = idx >> 4;
        int c4 = (idx & 15) << 2;
        float4 kv = *(const float4*)(kbase + (long)n * DMOD + c4);
        Ksh[n * KPAD + c4 + 0] = kv.x; Ksh[n * KPAD + c4 + 1] = kv.y;
        Ksh[n * KPAD + c4 + 2] = kv.z; Ksh[n * KPAD + c4 + 3] = kv.w;
        float4 vv = *(const float4*)(vbase + (long)n * DMOD + c4);
        *(float4*)(Vsh + n * 64 + c4) = vv;
    }
    __syncthreads();

    const int qa = blockIdx.x * 16 + 2 * w;
    const int qb = qa + 1;
    if (qa < NQ) {
        __half* pbA = pbufh + (w * 2 + 0) * NK;
        __half* pbB = pbufh + (w * 2 + 1) * NK;

        const float* qrowA = g_qsig + (long)(b * NQ + qa) * DMOD + h * DK;
        const float* qrowB = g_qsig + (long)(b * NQ + qb) * DMOD + h * DK;
        float qa0 = qrowA[lane], qa1 = qrowA[lane + 32];
        float qb0 = qrowB[lane], qb1 = qrowB[lane + 32];
        float qha0 = 0.5f*qa0, qha1 = 0.5f*qa1, qhb0 = 0.5f*qb0, qhb1 = 0.5f*qb1;

        float sa[7], sb[7];
        int kb[7];
#pragma unroll
        for (int i = 0; i < 7; i++) { sa[i]=0.f; sb[i]=0.f; kb[i]=(i*32+lane)*KPAD; }
#pragma unroll 4
        for (int d = 0; d < 32; d++) {
            float qda = __shfl_sync(0xffffffffu, qa0, d);
            float qdb = __shfl_sync(0xffffffffu, qb0, d);
#pragma unroll
            for (int i = 0; i < 7; i++) {
                float kv = Ksh[kb[i] + d];
                sa[i] += qda * kv;
                sb[i] += qdb * kv;
            }
        }
#pragma unroll 4
        for (int d = 0; d < 32; d++) {
            float qda = __shfl_sync(0xffffffffu, qa1, d);
            float qdb = __shfl_sync(0xffffffffu, qb1, d);
#pragma unroll
            for (int i = 0; i < 7; i++) {
                float kv = Ksh[kb[i] + 32 + d];
                sa[i] += qda * kv;
                sb[i] += qdb * kv;
            }
        }

        const float* scrA = scale + (long)(h * NQ + qa) * NK;
        const float* scrB = scale + (long)(h * NQ + qb) * NK;
        float mxa = -1e30f, mxb = -1e30f;
#pragma unroll
        for (int i = 0; i < 7; i++) {
            int k = i * 32 + lane;
            if (k < NK) {
                sa[i] *= scrA[k]; mxa = fmaxf(mxa, sa[i]);
                sb[i] *= scrB[k]; mxb = fmaxf(mxb, sb[i]);
            }
        }
#pragma unroll
        for (int o = 16; o; o >>= 1) {
            mxa = fmaxf(mxa, __shfl_xor_sync(0xffffffffu, mxa, o));
            mxb = fmaxf(mxb, __shfl_xor_sync(0xffffffffu, mxb, o));
        }

        float suma = 0.f, sumb = 0.f;
#pragma unroll
        for (int i = 0; i < 7; i++) {
            int k = i * 32 + lane;
            if (k < NK) {
                float pa = __expf(sa[i] - mxa);
                float pb = __expf(sb[i] - mxb);
                pbA[k] = __float2half(0.5f * pa);
                pbB[k] = __float2half(0.5f * pb);
                suma += pa; sumb += pb;
            }
        }
#pragma unroll
        for (int o = 16; o; o >>= 1) {
            suma += __shfl_xor_sync(0xffffffffu, suma, o);
            sumb += __shfl_xor_sync(0xffffffffu, sumb, o);
        }
        float rdena = __fdividef(1.f, suma);
        float rdenb = __fdividef(1.f, sumb);
        __syncwarp();

        float aa0 = 0.f, aa1 = 0.f, ab0 = 0.f, ab1 = 0.f;
#pragma unroll 4
        for (int k = 0; k < NK; k++) {
            float hpa = __half2float(pbA[k]);
            float hpb = __half2float(pbB[k]);
            float k0 = Ksh[k * KPAD + lane];
            float k1 = Ksh[k * KPAD + lane + 32];
            float v0 = Vsh[k * 64 + lane];
            float v1 = Vsh[k * 64 + lane + 32];
            float t;
            t = tanhap(qha0 * k0); aa0 = fmaf(fmaf(hpa, t, hpa), v0, aa0);
            t = tanhap(qha1 * k1); aa1 = fmaf(fmaf(hpa, t, hpa), v1, aa1);
            t = tanhap(qhb0 * k0); ab0 = fmaf(fmaf(hpb, t, hpb), v0, ab0);
            t = tanhap(qhb1 * k1); ab1 = fmaf(fmaf(hpb, t, hpb), v1, ab1);
        }

        float* orA = g_img + (long)(b * NQ + qa) * DMOD + h * DK;
        float* orB = g_img + (long)(b * NQ + qb) * DMOD + h * DK;
        orA[lane]      = aa0 * rdena;
        orA[lane + 32] = aa1 * rdena;
        orB[lane]      = ab0 * rdenb;
        orB[lane + 32] = ab1 * rdenb;
    }
}

// ---------------------------------------------------------------------------
extern "C" void kernel_launch(void* const* d_in, const int* in_sizes, int n_in,
                              void* d_out, int out_size)
{
    const float* queries = (const float*)d_in[0];
    const float* keys    = (const float*)d_in[1];
    const float* values  = (const float*)d_in[2];
    const float* Wq      = (const float*)d_in[3];
    const float* bq      = (const float*)d_in[4];
    const float* Wk      = (const float*)d_in[5];
    const float* bk      = (const float*)d_in[6];
    const float* Wv      = (const float*)d_in[7];
    const float* bv      = (const float*)d_in[8];
    const float* Wo      = (const float*)d_in[9];
    const float* bo      = (const float*)d_in[10];
    const float* scale   = (const float*)d_in[11];
    float* out = (float*)d_out;

    float* qsig; cudaGetSymbolAddress((void**)&qsig, g_qsig);
    float* kp;   cudaGetSymbolAddress((void**)&kp,   g_kp);
    float* vp;   cudaGetSymbolAddress((void**)&vp,   g_vp);
    float* img;  cudaGetSymbolAddress((void**)&img,  g_img);

    const int smem_attn = (NK * KPAD + NK * 64) * (int)sizeof(float)
                        + 16 * NK * (int)sizeof(__half);
    cudaFuncSetAttribute(attn_kernel, cudaFuncAttributeMaxDynamicSharedMemorySize, smem_attn);

    // Fused Q/K/V projections: grid (8 N-tiles, 3 matrices, 13 M-tiles),
    // 256 threads -> 312 blocks x 8 warps; M-tail tiles schedule last.
    dim3 gg(DMOD / 64, 3, (MROWS + 63) / 64);
    gemm_kernel<0><<<gg, 256>>>(queries, keys, values,
                                Wq, Wk, Wv, bq, bk, bv,
                                qsig, kp, vp);

    dim3 g2((NQ + 15) / 16, BB * NH);
    attn_kernel<<<g2, 256, smem_attn>>>(scale);

    dim3 g3(DMOD / 64, 1, (MROWS + 63) / 64);
    gemm_kernel<1><<<g3, 256>>>(img, img, img,
                                Wo, Wo, Wo, bo, bo, bo,
                                out, out, out);
}

// round 9
// speedup vs baseline: 1.9077x; 1.0400x over previous
#include <cuda_runtime.h>
#include <cuda_fp16.h>

#define BB   4
#define NQ   196
#define NK   196
#define DMOD 512
#define NH   8
#define DK   64
#define MROWS (BB*NQ)   // 784
#define KPAD 65
#define SPAD 68         // smem row pad in floats (17 float4)

__device__ float g_qsig[BB*NQ*DMOD];
__device__ float g_kp[BB*NQ*DMOD];
__device__ float g_vp[BB*NQ*DMOD];
__device__ float g_img[BB*NQ*DMOD];
__device__ float g_part[4 * BB*NQ*DMOD];   // split-K partials for out proj

__device__ __forceinline__ float tanhap(float x) {
    float y; asm("tanh.approx.f32 %0, %1;" : "=f"(y) : "f"(x)); return y;
}

// ===========================================================================
// Fused Q/K/V projection GEMM: Y = X @ W^T + b.
// BM=64, BN=64, BK=32, 256 threads, 4x4 micro-tile.
// Double-buffered smem (1 barrier per BK tile) + register fragment d-buffer.
// Grid: (N=8, matrix=3, M=13).
// ===========================================================================
__global__ void __launch_bounds__(256, 2) proj_gemm_kernel(
    const float* __restrict__ X0, const float* __restrict__ X1, const float* __restrict__ X2,
    const float* __restrict__ W0, const float* __restrict__ W1, const float* __restrict__ W2,
    const float* __restrict__ b0, const float* __restrict__ b1, const float* __restrict__ b2,
    float* __restrict__ Y0, float* __restrict__ Y1, float* __restrict__ Y2)
{
    const float* X; const float* W; const float* bias; float* Y;
    if (blockIdx.y == 0)      { X = X0; W = W0; bias = b0; Y = Y0; }
    else if (blockIdx.y == 1) { X = X1; W = W1; bias = b1; Y = Y1; }
    else                      { X = X2; W = W2; bias = b2; Y = Y2; }

    __shared__ float As[2][32][SPAD];
    __shared__ float Bs[2][32][SPAD];

    const int tid = threadIdx.x;
    const int tx  = tid & 15;
    const int ty  = tid >> 4;
    const int gm_base = blockIdx.z * 64;
    const int gn_base = blockIdx.x * 64;

    const int lr  = tid >> 2;
    const int f4c = tid & 3;
    const int c0  = f4c * 4;

    float acc[4][4];
#pragma unroll
    for (int i = 0; i < 4; i++)
#pragma unroll
        for (int j = 0; j < 4; j++) acc[i][j] = 0.f;

    const int gm = gm_base + lr;
    const bool mv = (gm < MROWS);
    const float* xp0 = X + (long)gm * DMOD + c0;
    const float* wp0 = W + (long)(gn_base + lr) * DMOD + c0;

    float4 xa0, xa1, wb0, wb1;
    // prologue: tile 0
    xa0 = mv ? *(const float4*)(xp0)      : make_float4(0.f,0.f,0.f,0.f);
    xa1 = mv ? *(const float4*)(xp0 + 16) : make_float4(0.f,0.f,0.f,0.f);
    wb0 = *(const float4*)(wp0);
    wb1 = *(const float4*)(wp0 + 16);
    {
        float* a = &As[0][0][0]; float* b = &Bs[0][0][0];
        a[(c0+0)*SPAD+lr]=xa0.x; a[(c0+1)*SPAD+lr]=xa0.y; a[(c0+2)*SPAD+lr]=xa0.z; a[(c0+3)*SPAD+lr]=xa0.w;
        a[(c0+16)*SPAD+lr]=xa1.x; a[(c0+17)*SPAD+lr]=xa1.y; a[(c0+18)*SPAD+lr]=xa1.z; a[(c0+19)*SPAD+lr]=xa1.w;
        b[(c0+0)*SPAD+lr]=wb0.x; b[(c0+1)*SPAD+lr]=wb0.y; b[(c0+2)*SPAD+lr]=wb0.z; b[(c0+3)*SPAD+lr]=wb0.w;
        b[(c0+16)*SPAD+lr]=wb1.x; b[(c0+17)*SPAD+lr]=wb1.y; b[(c0+18)*SPAD+lr]=wb1.z; b[(c0+19)*SPAD+lr]=wb1.w;
    }
    __syncthreads();

    const int NT = DMOD / 32;   // 16
    for (int t = 0; t < NT; t++) {
        const int cur = t & 1;
        const bool has_next = (t + 1 < NT);

        if (has_next) {
            int kt = (t + 1) * 32;
            xa0 = mv ? *(const float4*)(xp0 + kt)      : make_float4(0.f,0.f,0.f,0.f);
            xa1 = mv ? *(const float4*)(xp0 + kt + 16) : make_float4(0.f,0.f,0.f,0.f);
            wb0 = *(const float4*)(wp0 + kt);
            wb1 = *(const float4*)(wp0 + kt + 16);
        }

        const float4* As4 = (const float4*)&As[cur][0][0];
        const float4* Bs4 = (const float4*)&Bs[cur][0][0];
        float4 av = As4[ty], bv = Bs4[tx];   // kk = 0
#pragma unroll
        for (int kk = 0; kk < 32; kk++) {
            float4 av2, bv2;
            if (kk < 31) {
                av2 = As4[(kk + 1) * (SPAD/4) + ty];
                bv2 = Bs4[(kk + 1) * (SPAD/4) + tx];
            }
            float aa[4] = {av.x, av.y, av.z, av.w};
            float bb[4] = {bv.x, bv.y, bv.z, bv.w};
#pragma unroll
            for (int i = 0; i < 4; i++)
#pragma unroll
                for (int j = 0; j < 4; j++)
                    acc[i][j] = fmaf(aa[i], bb[j], acc[i][j]);
            av = av2; bv = bv2;
        }

        if (has_next) {
            const int nxt = 1 - cur;
            float* a = &As[nxt][0][0]; float* b = &Bs[nxt][0][0];
            a[(c0+0)*SPAD+lr]=xa0.x; a[(c0+1)*SPAD+lr]=xa0.y; a[(c0+2)*SPAD+lr]=xa0.z; a[(c0+3)*SPAD+lr]=xa0.w;
            a[(c0+16)*SPAD+lr]=xa1.x; a[(c0+17)*SPAD+lr]=xa1.y; a[(c0+18)*SPAD+lr]=xa1.z; a[(c0+19)*SPAD+lr]=xa1.w;
            b[(c0+0)*SPAD+lr]=wb0.x; b[(c0+1)*SPAD+lr]=wb0.y; b[(c0+2)*SPAD+lr]=wb0.z; b[(c0+3)*SPAD+lr]=wb0.w;
            b[(c0+16)*SPAD+lr]=wb1.x; b[(c0+17)*SPAD+lr]=wb1.y; b[(c0+18)*SPAD+lr]=wb1.z; b[(c0+19)*SPAD+lr]=wb1.w;
        }
        __syncthreads();
    }

    const int n0 = gn_base + tx * 4;
    float4 bv4 = *(const float4*)(bias + n0);
#pragma unroll
    for (int i = 0; i < 4; i++) {
        int m = gm_base + ty * 4 + i;
        if (m >= MROWS) continue;
        *(float4*)(Y + (long)m * DMOD + n0) = make_float4(
            acc[i][0] + bv4.x, acc[i][1] + bv4.y,
            acc[i][2] + bv4.z, acc[i][3] + bv4.w);
    }
}

// ===========================================================================
// Out-projection split-K partial GEMM: g_part[ks] = img @ Wo^T over K-range
// [ks*128, ks*128+128). Grid: (N=8, ks=4, M=13) = 416 blocks.
// Same pipeline structure as proj.
// ===========================================================================
__global__ void __launch_bounds__(256, 2) out_partial_kernel(const float* __restrict__ Wo)
{
    __shared__ float As[2][32][SPAD];
    __shared__ float Bs[2][32][SPAD];

    const int tid = threadIdx.x;
    const int tx  = tid & 15;
    const int ty  = tid >> 4;
    const int gm_base = blockIdx.z * 64;
    const int gn_base = blockIdx.x * 64;
    const int ks      = blockIdx.y;
    const int kbase   = ks * 128;

    const int lr  = tid >> 2;
    const int f4c = tid & 3;
    const int c0  = f4c * 4;

    float acc[4][4];
#pragma unroll
    for (int i = 0; i < 4; i++)
#pragma unroll
        for (int j = 0; j < 4; j++) acc[i][j] = 0.f;

    const int gm = gm_base + lr;
    const bool mv = (gm < MROWS);
    const float* xp0 = g_img + (long)gm * DMOD + kbase + c0;
    const float* wp0 = Wo + (long)(gn_base + lr) * DMOD + kbase + c0;

    float4 xa0, xa1, wb0, wb1;
    xa0 = mv ? *(const float4*)(xp0)      : make_float4(0.f,0.f,0.f,0.f);
    xa1 = mv ? *(const float4*)(xp0 + 16) : make_float4(0.f,0.f,0.f,0.f);
    wb0 = *(const float4*)(wp0);
    wb1 = *(const float4*)(wp0 + 16);
    {
        float* a = &As[0][0][0]; float* b = &Bs[0][0][0];
        a[(c0+0)*SPAD+lr]=xa0.x; a[(c0+1)*SPAD+lr]=xa0.y; a[(c0+2)*SPAD+lr]=xa0.z; a[(c0+3)*SPAD+lr]=xa0.w;
        a[(c0+16)*SPAD+lr]=xa1.x; a[(c0+17)*SPAD+lr]=xa1.y; a[(c0+18)*SPAD+lr]=xa1.z; a[(c0+19)*SPAD+lr]=xa1.w;
        b[(c0+0)*SPAD+lr]=wb0.x; b[(c0+1)*SPAD+lr]=wb0.y; b[(c0+2)*SPAD+lr]=wb0.z; b[(c0+3)*SPAD+lr]=wb0.w;
        b[(c0+16)*SPAD+lr]=wb1.x; b[(c0+17)*SPAD+lr]=wb1.y; b[(c0+18)*SPAD+lr]=wb1.z; b[(c0+19)*SPAD+lr]=wb1.w;
    }
    __syncthreads();

    const int NT = 4;   // 128 / 32
    for (int t = 0; t < NT; t++) {
        const int cur = t & 1;
        const bool has_next = (t + 1 < NT);

        if (has_next) {
            int kt = (t + 1) * 32;
            xa0 = mv ? *(const float4*)(xp0 + kt)      : make_float4(0.f,0.f,0.f,0.f);
            xa1 = mv ? *(const float4*)(xp0 + kt + 16) : make_float4(0.f,0.f,0.f,0.f);
            wb0 = *(const float4*)(wp0 + kt);
            wb1 = *(const float4*)(wp0 + kt + 16);
        }

        const float4* As4 = (const float4*)&As[cur][0][0];
        const float4* Bs4 = (const float4*)&Bs[cur][0][0];
        float4 av = As4[ty], bv = Bs4[tx];
#pragma unroll
        for (int kk = 0; kk < 32; kk++) {
            float4 av2, bv2;
            if (kk < 31) {
                av2 = As4[(kk + 1) * (SPAD/4) + ty];
                bv2 = Bs4[(kk + 1) * (SPAD/4) + tx];
            }
            float aa[4] = {av.x, av.y, av.z, av.w};
            float bb[4] = {bv.x, bv.y, bv.z, bv.w};
#pragma unroll
            for (int i = 0; i < 4; i++)
#pragma unroll
                for (int j = 0; j < 4; j++)
                    acc[i][j] = fmaf(aa[i], bb[j], acc[i][j]);
            av = av2; bv = bv2;
        }

        if (has_next) {
            const int nxt = 1 - cur;
            float* a = &As[nxt][0][0]; float* b = &Bs[nxt][0][0];
            a[(c0+0)*SPAD+lr]=xa0.x; a[(c0+1)*SPAD+lr]=xa0.y; a[(c0+2)*SPAD+lr]=xa0.z; a[(c0+3)*SPAD+lr]=xa0.w;
            a[(c0+16)*SPAD+lr]=xa1.x; a[(c0+17)*SPAD+lr]=xa1.y; a[(c0+18)*SPAD+lr]=xa1.z; a[(c0+19)*SPAD+lr]=xa1.w;
            b[(c0+0)*SPAD+lr]=wb0.x; b[(c0+1)*SPAD+lr]=wb0.y; b[(c0+2)*SPAD+lr]=wb0.z; b[(c0+3)*SPAD+lr]=wb0.w;
            b[(c0+16)*SPAD+lr]=wb1.x; b[(c0+17)*SPAD+lr]=wb1.y; b[(c0+18)*SPAD+lr]=wb1.z; b[(c0+19)*SPAD+lr]=wb1.w;
        }
        __syncthreads();
    }

    float* Y = g_part + (long)ks * (MROWS * DMOD);
    const int n0 = gn_base + tx * 4;
#pragma unroll
    for (int i = 0; i < 4; i++) {
        int m = gm_base + ty * 4 + i;
        if (m >= MROWS) continue;
        *(float4*)(Y + (long)m * DMOD + n0) = make_float4(
            acc[i][0], acc[i][1], acc[i][2], acc[i][3]);
    }
}

// ===========================================================================
// Reduce 4 split-K partials + bias, then final gate: out = sigmoid(qs*o)*o
// ===========================================================================
__global__ void __launch_bounds__(256) reduce_gate_kernel(
    const float* __restrict__ bo, float* __restrict__ out)
{
    const int idx = blockIdx.x * 256 + threadIdx.x;      // float4 index
    const int total4 = MROWS * DMOD / 4;
    if (idx >= total4) return;
    const int SZ4 = total4;
    const float4* p = (const float4*)g_part;
    float4 s0 = p[idx];
    float4 s1 = p[idx + SZ4];
    float4 s2 = p[idx + 2*SZ4];
    float4 s3 = p[idx + 3*SZ4];
    const int c4 = idx % (DMOD / 4);
    float4 bb = ((const float4*)bo)[c4];
    float o0 = s0.x + s1.x + s2.x + s3.x + bb.x;
    float o1 = s0.y + s1.y + s2.y + s3.y + bb.y;
    float o2 = s0.z + s1.z + s2.z + s3.z + bb.z;
    float o3 = s0.w + s1.w + s2.w + s3.w + bb.w;
    float4 qs = ((const float4*)g_qsig)[idx];
    o0 *= 0.5f + 0.5f * tanhap(0.5f * qs.x * o0);
    o1 *= 0.5f + 0.5f * tanhap(0.5f * qs.y * o1);
    o2 *= 0.5f + 0.5f * tanhap(0.5f * qs.z * o2);
    o3 *= 0.5f + 0.5f * tanhap(0.5f * qs.w * o3);
    ((float4*)out)[idx] = make_float4(o0, o1, o2, o3);
}

// ===========================================================================
// Attention core (unchanged from R8). Grid (13, 32), 256 threads.
// ===========================================================================
__global__ void __launch_bounds__(256) attn_kernel(const float* __restrict__ scale)
{
    extern __shared__ float sm[];
    float*  Ksh   = sm;
    float*  Vsh   = Ksh + NK * KPAD;
    __half* pbufh = (__half*)(Vsh + NK * 64);

    const int bh   = blockIdx.y;
    const int b    = bh >> 3;
    const int h    = bh & 7;
    const int tid  = threadIdx.x;
    const int w    = tid >> 5;
    const int lane = tid & 31;

    const float* kbase = g_kp + (long)(b * NQ) * DMOD + h * DK;
    const float* vbase = g_vp + (long)(b * NQ) * DMOD + h * DK;

    for (int idx = tid; idx < NK * 16; idx += 256) {
        int n  = idx >> 4;
        int c4 = (idx & 15) << 2;
        float4 kv = *(const float4*)(kbase + (long)n * DMOD + c4);
        Ksh[n * KPAD + c4 + 0] = kv.x; Ksh[n * KPAD + c4 + 1] = kv.y;
        Ksh[n * KPAD + c4 + 2] = kv.z; Ksh[n * KPAD + c4 + 3] = kv.w;
        float4 vv = *(const float4*)(vbase + (long)n * DMOD + c4);
        *(float4*)(Vsh + n * 64 + c4) = vv;
    }
    __syncthreads();

    const int qa = blockIdx.x * 16 + 2 * w;
    const int qb = qa + 1;
    if (qa < NQ) {
        __half* pbA = pbufh + (w * 2 + 0) * NK;
        __half* pbB = pbufh + (w * 2 + 1) * NK;

        const float* qrowA = g_qsig + (long)(b * NQ + qa) * DMOD + h * DK;
        const float* qrowB = g_qsig + (long)(b * NQ + qb) * DMOD + h * DK;
        float qa0 = qrowA[lane], qa1 = qrowA[lane + 32];
        float qb0 = qrowB[lane], qb1 = qrowB[lane + 32];
        float qha0 = 0.5f*qa0, qha1 = 0.5f*qa1, qhb0 = 0.5f*qb0, qhb1 = 0.5f*qb1;

        float sa[7], sb[7];
        int kb[7];
#pragma unroll
        for (int i = 0; i < 7; i++) { sa[i]=0.f; sb[i]=0.f; kb[i]=(i*32+lane)*KPAD; }
#pragma unroll 4
        for (int d = 0; d < 32; d++) {
            float qda = __shfl_sync(0xffffffffu, qa0, d);
            float qdb = __shfl_sync(0xffffffffu, qb0, d);
#pragma unroll
            for (int i = 0; i < 7; i++) {
                float kv = Ksh[kb[i] + d];
                sa[i] += qda * kv;
                sb[i] += qdb * kv;
            }
        }
#pragma unroll 4
        for (int d = 0; d < 32; d++) {
            float qda = __shfl_sync(0xffffffffu, qa1, d);
            float qdb = __shfl_sync(0xffffffffu, qb1, d);
#pragma unroll
            for (int i = 0; i < 7; i++) {
                float kv = Ksh[kb[i] + 32 + d];
                sa[i] += qda * kv;
                sb[i] += qdb * kv;
            }
        }

        const float* scrA = scale + (long)(h * NQ + qa) * NK;
        const float* scrB = scale + (long)(h * NQ + qb) * NK;
        float mxa = -1e30f, mxb = -1e30f;
#pragma unroll
        for (int i = 0; i < 7; i++) {
            int k = i * 32 + lane;
            if (k < NK) {
                sa[i] *= scrA[k]; mxa = fmaxf(mxa, sa[i]);
                sb[i] *= scrB[k]; mxb = fmaxf(mxb, sb[i]);
            }
        }
#pragma unroll
        for (int o = 16; o; o >>= 1) {
            mxa = fmaxf(mxa, __shfl_xor_sync(0xffffffffu, mxa, o));
            mxb = fmaxf(mxb, __shfl_xor_sync(0xffffffffu, mxb, o));
        }

        float suma = 0.f, sumb = 0.f;
#pragma unroll
        for (int i = 0; i < 7; i++) {
            int k = i * 32 + lane;
            if (k < NK) {
                float pa = __expf(sa[i] - mxa);
                float pb = __expf(sb[i] - mxb);
                pbA[k] = __float2half(0.5f * pa);
                pbB[k] = __float2half(0.5f * pb);
                suma += pa; sumb += pb;
            }
        }
#pragma unroll
        for (int o = 16; o; o >>= 1) {
            suma += __shfl_xor_sync(0xffffffffu, suma, o);
            sumb += __shfl_xor_sync(0xffffffffu, sumb, o);
        }
        float rdena = __fdividef(1.f, suma);
        float rdenb = __fdividef(1.f, sumb);
        __syncwarp();

        float aa0 = 0.f, aa1 = 0.f, ab0 = 0.f, ab1 = 0.f;
#pragma unroll 4
        for (int k = 0; k < NK; k++) {
            float hpa = __half2float(pbA[k]);
            float hpb = __half2float(pbB[k]);
            float k0 = Ksh[k * KPAD + lane];
            float k1 = Ksh[k * KPAD + lane + 32];
            float v0 = Vsh[k * 64 + lane];
            float v1 = Vsh[k * 64 + lane + 32];
            float t;
            t = tanhap(qha0 * k0); aa0 = fmaf(fmaf(hpa, t, hpa), v0, aa0);
            t = tanhap(qha1 * k1); aa1 = fmaf(fmaf(hpa, t, hpa), v1, aa1);
            t = tanhap(qhb0 * k0); ab0 = fmaf(fmaf(hpb, t, hpb), v0, ab0);
            t = tanhap(qhb1 * k1); ab1 = fmaf(fmaf(hpb, t, hpb), v1, ab1);
        }

        float* orA = g_img + (long)(b * NQ + qa) * DMOD + h * DK;
        float* orB = g_img + (long)(b * NQ + qb) * DMOD + h * DK;
        orA[lane]      = aa0 * rdena;
        orA[lane + 32] = aa1 * rdena;
        orB[lane]      = ab0 * rdenb;
        orB[lane + 32] = ab1 * rdenb;
    }
}

// ---------------------------------------------------------------------------
extern "C" void kernel_launch(void* const* d_in, const int* in_sizes, int n_in,
                              void* d_out, int out_size)
{
    const float* queries = (const float*)d_in[0];
    const float* keys    = (const float*)d_in[1];
    const float* values  = (const float*)d_in[2];
    const float* Wq      = (const float*)d_in[3];
    const float* bq      = (const float*)d_in[4];
    const float* Wk      = (const float*)d_in[5];
    const float* bk      = (const float*)d_in[6];
    const float* Wv      = (const float*)d_in[7];
    const float* bv      = (const float*)d_in[8];
    const float* Wo      = (const float*)d_in[9];
    const float* bo      = (const float*)d_in[10];
    const float* scale   = (const float*)d_in[11];
    float* out = (float*)d_out;

    float* qsig; cudaGetSymbolAddress((void**)&qsig, g_qsig);
    float* kp;   cudaGetSymbolAddress((void**)&kp,   g_kp);
    float* vp;   cudaGetSymbolAddress((void**)&vp,   g_vp);

    const int smem_attn = (NK * KPAD + NK * 64) * (int)sizeof(float)
                        + 16 * NK * (int)sizeof(__half);
    cudaFuncSetAttribute(attn_kernel, cudaFuncAttributeMaxDynamicSharedMemorySize, smem_attn);

    dim3 gg(DMOD / 64, 3, (MROWS + 63) / 64);
    proj_gemm_kernel<<<gg, 256>>>(queries, keys, values,
                                  Wq, Wk, Wv, bq, bk, bv,
                                  qsig, kp, vp);

    dim3 g2((NQ + 15) / 16, BB * NH);
    attn_kernel<<<g2, 256, smem_attn>>>(scale);

    dim3 g3(DMOD / 64, 4, (MROWS + 63) / 64);
    out_partial_kernel<<<g3, 256>>>(Wo);

    const int total4 = MROWS * DMOD / 4;
    reduce_gate_kernel<<<(total4 + 255) / 256, 256>>>(bo, out);
}

// round 11
// speedup vs baseline: 2.0547x; 1.0770x over previous
#include <cuda_runtime.h>
#include <cuda_fp16.h>
#include <cuda_bf16.h>

#define BB   4
#define NQ   196
#define NK   196
#define DMOD 512
#define NH   8
#define DK   64
#define MROWS (BB*NQ)   // 784
#define KPAD 65

__device__ float g_qsig[BB*NQ*DMOD];
__device__ float g_kp[BB*NQ*DMOD];
__device__ float g_vp[BB*NQ*DMOD];
__device__ float g_img[BB*NQ*DMOD];

// split-bf16 operands
__device__ __nv_bfloat16 g_xhi[3 * MROWS * DMOD];
__device__ __nv_bfloat16 g_xlo[3 * MROWS * DMOD];
__device__ __nv_bfloat16 g_whi[4 * DMOD * DMOD];
__device__ __nv_bfloat16 g_wlo[4 * DMOD * DMOD];
__device__ __nv_bfloat16 g_imghi[MROWS * DMOD];
__device__ __nv_bfloat16 g_imglo[MROWS * DMOD];

__device__ __forceinline__ float tanhap(float x) {
    float y; asm("tanh.approx.f32 %0, %1;" : "=f"(y) : "f"(x)); return y;
}

__device__ __forceinline__ void mma_bf16(float* d,
    unsigned a0, unsigned a1, unsigned a2, unsigned a3,
    unsigned b0, unsigned b1)
{
    asm volatile(
        "mma.sync.aligned.m16n8k16.row.col.f32.bf16.bf16.f32 "
        "{%0,%1,%2,%3}, {%4,%5,%6,%7}, {%8,%9}, {%0,%1,%2,%3};\n"
        : "+f"(d[0]), "+f"(d[1]), "+f"(d[2]), "+f"(d[3])
        : "r"(a0), "r"(a1), "r"(a2), "r"(a3), "r"(b0), "r"(b1));
}

// ---------------------------------------------------------------------------
// fp32 -> (hi, lo) bf16 split, 8 elements per thread
// ---------------------------------------------------------------------------
__device__ __forceinline__ void convert8(const float* src,
    __nv_bfloat16* hi, __nv_bfloat16* lo)
{
    float4 v0 = *(const float4*)(src);
    float4 v1 = *(const float4*)(src + 4);
    float xs[8] = {v0.x, v0.y, v0.z, v0.w, v1.x, v1.y, v1.z, v1.w};
#pragma unroll
    for (int j = 0; j < 8; j++) {
        __nv_bfloat16 h = __float2bfloat16(xs[j]);
        float r = xs[j] - __bfloat162float(h);
        hi[j] = h;
        lo[j] = __float2bfloat16(r);
    }
}

// Converts 3 activation inputs (784x512) + 4 weights (512x512).
__global__ void __launch_bounds__(256) convert7_kernel(
    const float* __restrict__ q, const float* __restrict__ k, const float* __restrict__ v,
    const float* __restrict__ wq, const float* __restrict__ wk,
    const float* __restrict__ wv, const float* __restrict__ wo)
{
    const int seg = blockIdx.y;
    const float* src; __nv_bfloat16 *hi, *lo; long n;
    if (seg < 3) {
        src = (seg == 0) ? q : (seg == 1) ? k : v;
        hi = g_xhi + (long)seg * MROWS * DMOD;
        lo = g_xlo + (long)seg * MROWS * DMOD;
        n = (long)MROWS * DMOD;
    } else {
        int s = seg - 3;
        src = (s == 0) ? wq : (s == 1) ? wk : (s == 2) ? wv : wo;
        hi = g_whi + (long)s * DMOD * DMOD;
        lo = g_wlo + (long)s * DMOD * DMOD;
        n = (long)DMOD * DMOD;
    }
    long i = ((long)blockIdx.x * 256 + threadIdx.x) * 8;
    if (i >= n) return;
    convert8(src + i, hi + i, lo + i);
}

__global__ void __launch_bounds__(256) convert_img_kernel()
{
    long i = ((long)blockIdx.x * 256 + threadIdx.x) * 8;
    if (i >= (long)MROWS * DMOD) return;
    convert8(g_img + i, g_imghi + i, g_imglo + i);
}

// ---------------------------------------------------------------------------
// Tensor-core GEMM: Y = X @ W^T + b with split-bf16 (hi/lo) inputs.
// BM=64, BN=64, BK=64. 256 threads = 8 warps; warp tile 32(M)x16(N):
// 2 m-subtiles x 2 n-subtiles of m16n8k16, 3 hi/lo combos per step.
// SMEM tiles 64x72 bf16 (pitch 72: pitch/2 = 36 == 4 mod 32 -> the fragment
// LDS.32 pattern row*4+c hits all 32 banks exactly once).
// EPI=1: out-projection with fused sigmoid gate vs g_qsig.
// ---------------------------------------------------------------------------
template<int EPI>
__global__ void __launch_bounds__(256, 2) mma_gemm_kernel(
    const __nv_bfloat16* __restrict__ Xhi_, const __nv_bfloat16* __restrict__ Xlo_,
    const __nv_bfloat16* __restrict__ Whi_, const __nv_bfloat16* __restrict__ Wlo_,
    const float* __restrict__ b0_, const float* __restrict__ b1_, const float* __restrict__ b2_,
    float* __restrict__ Y0_, float* __restrict__ Y1_, float* __restrict__ Y2_)
{
    __shared__ __nv_bfloat16 sAhi[64][72];
    __shared__ __nv_bfloat16 sAlo[64][72];
    __shared__ __nv_bfloat16 sBhi[64][72];
    __shared__ __nv_bfloat16 sBlo[64][72];

    const int mat = blockIdx.y;
    const __nv_bfloat16* Xhi = Xhi_ + (long)mat * MROWS * DMOD;
    const __nv_bfloat16* Xlo = Xlo_ + (long)mat * MROWS * DMOD;
    const __nv_bfloat16* Whi = Whi_ + (long)mat * DMOD * DMOD;
    const __nv_bfloat16* Wlo = Wlo_ + (long)mat * DMOD * DMOD;
    const float* bias = (mat == 0) ? b0_ : (mat == 1) ? b1_ : b2_;
    float* Y = (mat == 0) ? Y0_ : (mat == 1) ? Y1_ : Y2_;

    const int tid  = threadIdx.x;
    const int gm_base = blockIdx.z * 64;
    const int gn_base = blockIdx.x * 64;

    // global tile load mapping: 4 threads per row, 16 bf16 (2x uint4) each
    const int lrow = tid >> 2;           // 0..63
    const int c8   = (tid & 3) * 16;     // 0,16,32,48

    // compute mapping
    const int w    = tid >> 5;
    const int lane = tid & 31;
    const int mrow = (w & 1) * 32;       // warp M offset in block
    const int ncol = (w >> 1) * 16;      // warp N offset in block
    const int g    = lane >> 2;          // 0..7
    const int cq   = lane & 3;           // k-pair index

    float acc[2][2][4];
#pragma unroll
    for (int mt = 0; mt < 2; mt++)
#pragma unroll
        for (int nt = 0; nt < 2; nt++)
#pragma unroll
            for (int i = 0; i < 4; i++) acc[mt][nt][i] = 0.f;

    const unsigned* A32h = (const unsigned*)&sAhi[0][0];
    const unsigned* A32l = (const unsigned*)&sAlo[0][0];
    const unsigned* B32h = (const unsigned*)&sBhi[0][0];
    const unsigned* B32l = (const unsigned*)&sBlo[0][0];

    const bool xvalid = (gm_base + lrow) < MROWS;
    const long xoff0 = (long)(gm_base + lrow) * DMOD + c8;
    const long woff0 = (long)(gn_base + lrow) * DMOD + c8;
    const uint4 z4 = make_uint4(0u, 0u, 0u, 0u);

    for (int kt = 0; kt < DMOD / 64; kt++) {
        // ---- stage tiles ----
        {
            const long xo = xoff0 + kt * 64;
            const long wo = woff0 + kt * 64;
            uint4 xh0 = xvalid ? *(const uint4*)(Xhi + xo)     : z4;
            uint4 xh1 = xvalid ? *(const uint4*)(Xhi + xo + 8) : z4;
            uint4 xl0 = xvalid ? *(const uint4*)(Xlo + xo)     : z4;
            uint4 xl1 = xvalid ? *(const uint4*)(Xlo + xo + 8) : z4;
            uint4 wh0 = *(const uint4*)(Whi + wo);
            uint4 wh1 = *(const uint4*)(Whi + wo + 8);
            uint4 wl0 = *(const uint4*)(Wlo + wo);
            uint4 wl1 = *(const uint4*)(Wlo + wo + 8);
            *(uint4*)&sAhi[lrow][c8]     = xh0;
            *(uint4*)&sAhi[lrow][c8 + 8] = xh1;
            *(uint4*)&sAlo[lrow][c8]     = xl0;
            *(uint4*)&sAlo[lrow][c8 + 8] = xl1;
            *(uint4*)&sBhi[lrow][c8]     = wh0;
            *(uint4*)&sBhi[lrow][c8 + 8] = wh1;
            *(uint4*)&sBlo[lrow][c8]     = wl0;
            *(uint4*)&sBlo[lrow][c8 + 8] = wl1;
        }
        __syncthreads();

        // ---- 4 k-steps of m16n8k16 ----
#pragma unroll
        for (int ks = 0; ks < 4; ks++) {
            const int ko = ks * 8 + cq;   // uint32 offset within row

            unsigned ah[2][4], al[2][4];
#pragma unroll
            for (int mt = 0; mt < 2; mt++) {
                int r = (mrow + mt * 16 + g) * 36;
                ah[mt][0] = A32h[r + ko];
                ah[mt][1] = A32h[r + 8 * 36 + ko];
                ah[mt][2] = A32h[r + ko + 4];
                ah[mt][3] = A32h[r + 8 * 36 + ko + 4];
                al[mt][0] = A32l[r + ko];
                al[mt][1] = A32l[r + 8 * 36 + ko];
                al[mt][2] = A32l[r + ko + 4];
                al[mt][3] = A32l[r + 8 * 36 + ko + 4];
            }
            unsigned bh[2][2], bl[2][2];
#pragma unroll
            for (int nt = 0; nt < 2; nt++) {
                int r = (ncol + nt * 8 + g) * 36;
                bh[nt][0] = B32h[r + ko];
                bh[nt][1] = B32h[r + ko + 4];
                bl[nt][0] = B32l[r + ko];
                bl[nt][1] = B32l[r + ko + 4];
            }
#pragma unroll
            for (int mt = 0; mt < 2; mt++)
#pragma unroll
                for (int nt = 0; nt < 2; nt++) {
                    mma_bf16(acc[mt][nt], ah[mt][0], ah[mt][1], ah[mt][2], ah[mt][3],
                             bh[nt][0], bh[nt][1]);
                    mma_bf16(acc[mt][nt], ah[mt][0], ah[mt][1], ah[mt][2], ah[mt][3],
                             bl[nt][0], bl[nt][1]);
                    mma_bf16(acc[mt][nt], al[mt][0], al[mt][1], al[mt][2], al[mt][3],
                             bh[nt][0], bh[nt][1]);
                }
        }
        __syncthreads();
    }

    // ---- epilogue ----
#pragma unroll
    for (int mt = 0; mt < 2; mt++)
#pragma unroll
        for (int nt = 0; nt < 2; nt++) {
            float* a = acc[mt][nt];
            const int c  = gn_base + ncol + nt * 8 + 2 * cq;
            const float bx = bias[c], by = bias[c + 1];
            const int r0 = gm_base + mrow + mt * 16 + g;
            if (r0 < MROWS) {
                float o0 = a[0] + bx, o1 = a[1] + by;
                if (EPI == 1) {
                    float2 qs = *(const float2*)(g_qsig + (long)r0 * DMOD + c);
                    o0 *= 0.5f + 0.5f * tanhap(0.5f * qs.x * o0);
                    o1 *= 0.5f + 0.5f * tanhap(0.5f * qs.y * o1);
                }
                *(float2*)(Y + (long)r0 * DMOD + c) = make_float2(o0, o1);
            }
            const int r1 = r0 + 8;
            if (r1 < MROWS) {
                float o0 = a[2] + bx, o1 = a[3] + by;
                if (EPI == 1) {
                    float2 qs = *(const float2*)(g_qsig + (long)r1 * DMOD + c);
                    o0 *= 0.5f + 0.5f * tanhap(0.5f * qs.x * o0);
                    o1 *= 0.5f + 0.5f * tanhap(0.5f * qs.y * o1);
                }
                *(float2*)(Y + (long)r1 * DMOD + c) = make_float2(o0, o1);
            }
        }
}

// ===========================================================================
// Attention core (unchanged). Grid (13, 32), 256 threads, ~105KB smem.
// ===========================================================================
__global__ void __launch_bounds__(256) attn_kernel(const float* __restrict__ scale)
{
    extern __shared__ float sm[];
    float*  Ksh   = sm;
    float*  Vsh   = Ksh + NK * KPAD;
    __half* pbufh = (__half*)(Vsh + NK * 64);

    const int bh   = blockIdx.y;
    const int b    = bh >> 3;
    const int h    = bh & 7;
    const int tid  = threadIdx.x;
    const int w    = tid >> 5;
    const int lane = tid & 31;

    const float* kbase = g_kp + (long)(b * NQ) * DMOD + h * DK;
    const float* vbase = g_vp + (long)(b * NQ) * DMOD + h * DK;

    for (int idx = tid; idx < NK * 16; idx += 256) {
        int n  = idx >> 4;
        int c4 = (idx & 15) << 2;
        float4 kv = *(const float4*)(kbase + (long)n * DMOD + c4);
        Ksh[n * KPAD + c4 + 0] = kv.x; Ksh[n * KPAD + c4 + 1] = kv.y;
        Ksh[n * KPAD + c4 + 2] = kv.z; Ksh[n * KPAD + c4 + 3] = kv.w;
        float4 vv = *(const float4*)(vbase + (long)n * DMOD + c4);
        *(float4*)(Vsh + n * 64 + c4) = vv;
    }
    __syncthreads();

    const int qa = blockIdx.x * 16 + 2 * w;
    const int qb = qa + 1;
    if (qa < NQ) {
        __half* pbA = pbufh + (w * 2 + 0) * NK;
        __half* pbB = pbufh + (w * 2 + 1) * NK;

        const float* qrowA = g_qsig + (long)(b * NQ + qa) * DMOD + h * DK;
        const float* qrowB = g_qsig + (long)(b * NQ + qb) * DMOD + h * DK;
        float qa0 = qrowA[lane], qa1 = qrowA[lane + 32];
        float qb0 = qrowB[lane], qb1 = qrowB[lane + 32];
        float qha0 = 0.5f*qa0, qha1 = 0.5f*qa1, qhb0 = 0.5f*qb0, qhb1 = 0.5f*qb1;

        float sa[7], sb[7];
        int kb[7];
#pragma unroll
        for (int i = 0; i < 7; i++) { sa[i]=0.f; sb[i]=0.f; kb[i]=(i*32+lane)*KPAD; }
#pragma unroll 4
        for (int d = 0; d < 32; d++) {
            float qda = __shfl_sync(0xffffffffu, qa0, d);
            float qdb = __shfl_sync(0xffffffffu, qb0, d);
#pragma unroll
            for (int i = 0; i < 7; i++) {
                float kv = Ksh[kb[i] + d];
                sa[i] += qda * kv;
                sb[i] += qdb * kv;
            }
        }
#pragma unroll 4
        for (int d = 0; d < 32; d++) {
            float qda = __shfl_sync(0xffffffffu, qa1, d);
            float qdb = __shfl_sync(0xffffffffu, qb1, d);
#pragma unroll
            for (int i = 0; i < 7; i++) {
                float kv = Ksh[kb[i] + 32 + d];
                sa[i] += qda * kv;
                sb[i] += qdb * kv;
            }
        }

        const float* scrA = scale + (long)(h * NQ + qa) * NK;
        const float* scrB = scale + (long)(h * NQ + qb) * NK;
        float mxa = -1e30f, mxb = -1e30f;
#pragma unroll
        for (int i = 0; i < 7; i++) {
            int k = i * 32 + lane;
            if (k < NK) {
                sa[i] *= scrA[k]; mxa = fmaxf(mxa, sa[i]);
                sb[i] *= scrB[k]; mxb = fmaxf(mxb, sb[i]);
            }
        }
#pragma unroll
        for (int o = 16; o; o >>= 1) {
            mxa = fmaxf(mxa, __shfl_xor_sync(0xffffffffu, mxa, o));
            mxb = fmaxf(mxb, __shfl_xor_sync(0xffffffffu, mxb, o));
        }

        float suma = 0.f, sumb = 0.f;
#pragma unroll
        for (int i = 0; i < 7; i++) {
            int k = i * 32 + lane;
            if (k < NK) {
                float pa = __expf(sa[i] - mxa);
                float pb = __expf(sb[i] - mxb);
                pbA[k] = __float2half(0.5f * pa);
                pbB[k] = __float2half(0.5f * pb);
                suma += pa; sumb += pb;
            }
        }
#pragma unroll
        for (int o = 16; o; o >>= 1) {
            suma += __shfl_xor_sync(0xffffffffu, suma, o);
            sumb += __shfl_xor_sync(0xffffffffu, sumb, o);
        }
        float rdena = __fdividef(1.f, suma);
        float rdenb = __fdividef(1.f, sumb);
        __syncwarp();

        float aa0 = 0.f, aa1 = 0.f, ab0 = 0.f, ab1 = 0.f;
#pragma unroll 4
        for (int k = 0; k < NK; k++) {
            float hpa = __half2float(pbA[k]);
            float hpb = __half2float(pbB[k]);
            float k0 = Ksh[k * KPAD + lane];
            float k1 = Ksh[k * KPAD + lane + 32];
            float v0 = Vsh[k * 64 + lane];
            float v1 = Vsh[k * 64 + lane + 32];
            float t;
            t = tanhap(qha0 * k0); aa0 = fmaf(fmaf(hpa, t, hpa), v0, aa0);
            t = tanhap(qha1 * k1); aa1 = fmaf(fmaf(hpa, t, hpa), v1, aa1);
            t = tanhap(qhb0 * k0); ab0 = fmaf(fmaf(hpb, t, hpb), v0, ab0);
            t = tanhap(qhb1 * k1); ab1 = fmaf(fmaf(hpb, t, hpb), v1, ab1);
        }

        float* orA = g_img + (long)(b * NQ + qa) * DMOD + h * DK;
        float* orB = g_img + (long)(b * NQ + qb) * DMOD + h * DK;
        orA[lane]      = aa0 * rdena;
        orA[lane + 32] = aa1 * rdena;
        orB[lane]      = ab0 * rdenb;
        orB[lane + 32] = ab1 * rdenb;
    }
}

// ---------------------------------------------------------------------------
extern "C" void kernel_launch(void* const* d_in, const int* in_sizes, int n_in,
                              void* d_out, int out_size)
{
    const float* queries = (const float*)d_in[0];
    const float* keys    = (const float*)d_in[1];
    const float* values  = (const float*)d_in[2];
    const float* Wq      = (const float*)d_in[3];
    const float* bq      = (const float*)d_in[4];
    const float* Wk      = (const float*)d_in[5];
    const float* bk      = (const float*)d_in[6];
    const float* Wv      = (const float*)d_in[7];
    const float* bv      = (const float*)d_in[8];
    const float* Wo      = (const float*)d_in[9];
    const float* bo      = (const float*)d_in[10];
    const float* scale   = (const float*)d_in[11];
    float* out = (float*)d_out;

    float* qsig; cudaGetSymbolAddress((void**)&qsig, g_qsig);
    float* kp;   cudaGetSymbolAddress((void**)&kp,   g_kp);
    float* vp;   cudaGetSymbolAddress((void**)&vp,   g_vp);
    __nv_bfloat16* xhi;   cudaGetSymbolAddress((void**)&xhi,   g_xhi);
    __nv_bfloat16* xlo;   cudaGetSymbolAddress((void**)&xlo,   g_xlo);
    __nv_bfloat16* whi;   cudaGetSymbolAddress((void**)&whi,   g_whi);
    __nv_bfloat16* wlo;   cudaGetSymbolAddress((void**)&wlo,   g_wlo);
    __nv_bfloat16* imghi; cudaGetSymbolAddress((void**)&imghi, g_imghi);
    __nv_bfloat16* imglo; cudaGetSymbolAddress((void**)&imglo, g_imglo);

    const int smem_attn = (NK * KPAD + NK * 64) * (int)sizeof(float)
                        + 16 * NK * (int)sizeof(__half);
    cudaFuncSetAttribute(attn_kernel, cudaFuncAttributeMaxDynamicSharedMemorySize, smem_attn);

    // 1) split-bf16 conversion of inputs + weights
    dim3 gc((MROWS * DMOD / 8 + 255) / 256, 7);
    convert7_kernel<<<gc, 256>>>(queries, keys, values, Wq, Wk, Wv, Wo);

    // 2) fused Q/K/V projections on tensor cores
    dim3 gg(DMOD / 64, 3, (MROWS + 63) / 64);
    mma_gemm_kernel<0><<<gg, 256>>>(xhi, xlo, whi, wlo,
                                    bq, bk, bv, qsig, kp, vp);

    // 3) attention core
    dim3 g2((NQ + 15) / 16, BB * NH);
    attn_kernel<<<g2, 256, smem_attn>>>(scale);

    // 4) convert img, 5) out-projection + gate on tensor cores
    dim3 gi((MROWS * DMOD / 8 + 255) / 256, 1);
    convert_img_kernel<<<gi, 256>>>();

    dim3 g3(DMOD / 64, 1, (MROWS + 63) / 64);
    mma_gemm_kernel<1><<<g3, 256>>>(imghi, imglo, whi + 3L * DMOD * DMOD, wlo + 3L * DMOD * DMOD,
                                    bo, bo, bo, out, out, out);
}

// round 15
// speedup vs baseline: 2.3200x; 1.1291x over previous
#include <cuda_runtime.h>
#include <cuda_fp16.h>
#include <cuda_bf16.h>

#define BB   4
#define NQ   196
#define NK   196
#define DMOD 512
#define NH   8
#define DK   64
#define MROWS (BB*NQ)   // 784
#define KPAD 65

__device__ float g_qsig[BB*NQ*DMOD];
__device__ float g_kp[BB*NQ*DMOD];
__device__ float g_vp[BB*NQ*DMOD];

// split-bf16 operands
__device__ __nv_bfloat16 g_xhi[3 * MROWS * DMOD];
__device__ __nv_bfloat16 g_xlo[3 * MROWS * DMOD];
__device__ __nv_bfloat16 g_whi[4 * DMOD * DMOD];
__device__ __nv_bfloat16 g_wlo[4 * DMOD * DMOD];
__device__ __nv_bfloat16 g_imghi[MROWS * DMOD];
__device__ __nv_bfloat16 g_imglo[MROWS * DMOD];

__device__ __forceinline__ float tanhap(float x) {
    float y; asm("tanh.approx.f32 %0, %1;" : "=f"(y) : "f"(x)); return y;
}

__device__ __forceinline__ void mma_bf16(float* d,
    unsigned a0, unsigned a1, unsigned a2, unsigned a3,
    unsigned b0, unsigned b1)
{
    asm volatile(
        "mma.sync.aligned.m16n8k16.row.col.f32.bf16.bf16.f32 "
        "{%0,%1,%2,%3}, {%4,%5,%6,%7}, {%8,%9}, {%0,%1,%2,%3};\n"
        : "+f"(d[0]), "+f"(d[1]), "+f"(d[2]), "+f"(d[3])
        : "r"(a0), "r"(a1), "r"(a2), "r"(a3), "r"(b0), "r"(b1));
}

// ---------------------------------------------------------------------------
// fp32 -> (hi, lo) bf16 split, 8 elements per thread
// ---------------------------------------------------------------------------
__device__ __forceinline__ void convert8(const float* src,
    __nv_bfloat16* hi, __nv_bfloat16* lo)
{
    float4 v0 = *(const float4*)(src);
    float4 v1 = *(const float4*)(src + 4);
    float xs[8] = {v0.x, v0.y, v0.z, v0.w, v1.x, v1.y, v1.z, v1.w};
#pragma unroll
    for (int j = 0; j < 8; j++) {
        __nv_bfloat16 h = __float2bfloat16(xs[j]);
        float r = xs[j] - __bfloat162float(h);
        hi[j] = h;
        lo[j] = __float2bfloat16(r);
    }
}

// Converts 3 activation inputs (784x512) + 4 weights (512x512).
__global__ void __launch_bounds__(256) convert7_kernel(
    const float* __restrict__ q, const float* __restrict__ k, const float* __restrict__ v,
    const float* __restrict__ wq, const float* __restrict__ wk,
    const float* __restrict__ wv, const float* __restrict__ wo)
{
    const int seg = blockIdx.y;
    const float* src; __nv_bfloat16 *hi, *lo; long n;
    if (seg < 3) {
        src = (seg == 0) ? q : (seg == 1) ? k : v;
        hi = g_xhi + (long)seg * MROWS * DMOD;
        lo = g_xlo + (long)seg * MROWS * DMOD;
        n = (long)MROWS * DMOD;
    } else {
        int s = seg - 3;
        src = (s == 0) ? wq : (s == 1) ? wk : (s == 2) ? wv : wo;
        hi = g_whi + (long)s * DMOD * DMOD;
        lo = g_wlo + (long)s * DMOD * DMOD;
        n = (long)DMOD * DMOD;
    }
    long i = ((long)blockIdx.x * 256 + threadIdx.x) * 8;
    if (i >= n) return;
    convert8(src + i, hi + i, lo + i);
}

// ---------------------------------------------------------------------------
// Tensor-core GEMM: Y = X @ W^T + b, split-bf16 (hi/lo). (proven 2.1e-4)
// ---------------------------------------------------------------------------
template<int EPI>
__global__ void __launch_bounds__(256, 2) mma_gemm_kernel(
    const __nv_bfloat16* __restrict__ Xhi_, const __nv_bfloat16* __restrict__ Xlo_,
    const __nv_bfloat16* __restrict__ Whi_, const __nv_bfloat16* __restrict__ Wlo_,
    const float* __restrict__ b0_, const float* __restrict__ b1_, const float* __restrict__ b2_,
    float* __restrict__ Y0_, float* __restrict__ Y1_, float* __restrict__ Y2_)
{
    __shared__ __nv_bfloat16 sAhi[64][72];
    __shared__ __nv_bfloat16 sAlo[64][72];
    __shared__ __nv_bfloat16 sBhi[64][72];
    __shared__ __nv_bfloat16 sBlo[64][72];

    const int mat = blockIdx.y;
    const __nv_bfloat16* Xhi = Xhi_ + (long)mat * MROWS * DMOD;
    const __nv_bfloat16* Xlo = Xlo_ + (long)mat * MROWS * DMOD;
    const __nv_bfloat16* Whi = Whi_ + (long)mat * DMOD * DMOD;
    const __nv_bfloat16* Wlo = Wlo_ + (long)mat * DMOD * DMOD;
    const float* bias = (mat == 0) ? b0_ : (mat == 1) ? b1_ : b2_;
    float* Y = (mat == 0) ? Y0_ : (mat == 1) ? Y1_ : Y2_;

    const int tid  = threadIdx.x;
    const int gm_base = blockIdx.z * 64;
    const int gn_base = blockIdx.x * 64;

    const int lrow = tid >> 2;
    const int c8   = (tid & 3) * 16;

    const int w    = tid >> 5;
    const int lane = tid & 31;
    const int mrow = (w & 1) * 32;
    const int ncol = (w >> 1) * 16;
    const int g    = lane >> 2;
    const int cq   = lane & 3;

    float acc[2][2][4];
#pragma unroll
    for (int mt = 0; mt < 2; mt++)
#pragma unroll
        for (int nt = 0; nt < 2; nt++)
#pragma unroll
            for (int i = 0; i < 4; i++) acc[mt][nt][i] = 0.f;

    const unsigned* A32h = (const unsigned*)&sAhi[0][0];
    const unsigned* A32l = (const unsigned*)&sAlo[0][0];
    const unsigned* B32h = (const unsigned*)&sBhi[0][0];
    const unsigned* B32l = (const unsigned*)&sBlo[0][0];

    const bool xvalid = (gm_base + lrow) < MROWS;
    const long xoff0 = (long)(gm_base + lrow) * DMOD + c8;
    const long woff0 = (long)(gn_base + lrow) * DMOD + c8;
    const uint4 z4 = make_uint4(0u, 0u, 0u, 0u);

    for (int kt = 0; kt < DMOD / 64; kt++) {
        {
            const long xo = xoff0 + kt * 64;
            const long wo = woff0 + kt * 64;
            uint4 xh0 = xvalid ? *(const uint4*)(Xhi + xo)     : z4;
            uint4 xh1 = xvalid ? *(const uint4*)(Xhi + xo + 8) : z4;
            uint4 xl0 = xvalid ? *(const uint4*)(Xlo + xo)     : z4;
            uint4 xl1 = xvalid ? *(const uint4*)(Xlo + xo + 8) : z4;
            uint4 wh0 = *(const uint4*)(Whi + wo);
            uint4 wh1 = *(const uint4*)(Whi + wo + 8);
            uint4 wl0 = *(const uint4*)(Wlo + wo);
            uint4 wl1 = *(const uint4*)(Wlo + wo + 8);
            *(uint4*)&sAhi[lrow][c8]     = xh0;
            *(uint4*)&sAhi[lrow][c8 + 8] = xh1;
            *(uint4*)&sAlo[lrow][c8]     = xl0;
            *(uint4*)&sAlo[lrow][c8 + 8] = xl1;
            *(uint4*)&sBhi[lrow][c8]     = wh0;
            *(uint4*)&sBhi[lrow][c8 + 8] = wh1;
            *(uint4*)&sBlo[lrow][c8]     = wl0;
            *(uint4*)&sBlo[lrow][c8 + 8] = wl1;
        }
        __syncthreads();

#pragma unroll
        for (int ks = 0; ks < 4; ks++) {
            const int ko = ks * 8 + cq;

            unsigned ah[2][4], al[2][4];
#pragma unroll
            for (int mt = 0; mt < 2; mt++) {
                int r = (mrow + mt * 16 + g) * 36;
                ah[mt][0] = A32h[r + ko];
                ah[mt][1] = A32h[r + 8 * 36 + ko];
                ah[mt][2] = A32h[r + ko + 4];
                ah[mt][3] = A32h[r + 8 * 36 + ko + 4];
                al[mt][0] = A32l[r + ko];
                al[mt][1] = A32l[r + 8 * 36 + ko];
                al[mt][2] = A32l[r + ko + 4];
                al[mt][3] = A32l[r + 8 * 36 + ko + 4];
            }
            unsigned bh[2][2], bl[2][2];
#pragma unroll
            for (int nt = 0; nt < 2; nt++) {
                int r = (ncol + nt * 8 + g) * 36;
                bh[nt][0] = B32h[r + ko];
                bh[nt][1] = B32h[r + ko + 4];
                bl[nt][0] = B32l[r + ko];
                bl[nt][1] = B32l[r + ko + 4];
            }
#pragma unroll
            for (int mt = 0; mt < 2; mt++)
#pragma unroll
                for (int nt = 0; nt < 2; nt++) {
                    mma_bf16(acc[mt][nt], ah[mt][0], ah[mt][1], ah[mt][2], ah[mt][3],
                             bh[nt][0], bh[nt][1]);
                    mma_bf16(acc[mt][nt], ah[mt][0], ah[mt][1], ah[mt][2], ah[mt][3],
                             bl[nt][0], bl[nt][1]);
                    mma_bf16(acc[mt][nt], al[mt][0], al[mt][1], al[mt][2], al[mt][3],
                             bh[nt][0], bh[nt][1]);
                }
        }
        __syncthreads();
    }

#pragma unroll
    for (int mt = 0; mt < 2; mt++)
#pragma unroll
        for (int nt = 0; nt < 2; nt++) {
            float* a = acc[mt][nt];
            const int c  = gn_base + ncol + nt * 8 + 2 * cq;
            const float bx = bias[c], by = bias[c + 1];
            const int r0 = gm_base + mrow + mt * 16 + g;
            if (r0 < MROWS) {
                float o0 = a[0] + bx, o1 = a[1] + by;
                if (EPI == 1) {
                    float2 qs = *(const float2*)(g_qsig + (long)r0 * DMOD + c);
                    o0 *= 0.5f + 0.5f * tanhap(0.5f * qs.x * o0);
                    o1 *= 0.5f + 0.5f * tanhap(0.5f * qs.y * o1);
                }
                *(float2*)(Y + (long)r0 * DMOD + c) = make_float2(o0, o1);
            }
            const int r1 = r0 + 8;
            if (r1 < MROWS) {
                float o0 = a[2] + bx, o1 = a[3] + by;
                if (EPI == 1) {
                    float2 qs = *(const float2*)(g_qsig + (long)r1 * DMOD + c);
                    o0 *= 0.5f + 0.5f * tanhap(0.5f * qs.x * o0);
                    o1 *= 0.5f + 0.5f * tanhap(0.5f * qs.y * o1);
                }
                *(float2*)(Y + (long)r1 * DMOD + c) = make_float2(o0, o1);
            }
        }
}

// ===========================================================================
// Attention core — R11 precision (f32 K, f32 V, f16 p, f32 tanh; proven
// 2.1e-4) + fused bf16 hi/lo img epilogue (precision-neutral, kills the
// convert_img kernel). Grid (13, 32), 256 threads, ~105KB smem, 2 blocks/SM.
// ===========================================================================
__global__ void __launch_bounds__(256) attn_kernel(const float* __restrict__ scale)
{
    extern __shared__ float sm[];
    float*  Ksh   = sm;                        // NK*KPAD f32
    float*  Vsh   = Ksh + NK * KPAD;           // NK*64 f32
    __half* pbufh = (__half*)(Vsh + NK * 64);  // 16*NK halves (0.5*p)

    const int bh   = blockIdx.y;
    const int b    = bh >> 3;
    const int h    = bh & 7;
    const int tid  = threadIdx.x;
    const int w    = tid >> 5;
    const int lane = tid & 31;

    const float* kbase = g_kp + (long)(b * NQ) * DMOD + h * DK;
    const float* vbase = g_vp + (long)(b * NQ) * DMOD + h * DK;

    for (int idx = tid; idx < NK * 16; idx += 256) {
        int n  = idx >> 4;
        int c4 = (idx & 15) << 2;
        float4 kv = *(const float4*)(kbase + (long)n * DMOD + c4);
        Ksh[n * KPAD + c4 + 0] = kv.x; Ksh[n * KPAD + c4 + 1] = kv.y;
        Ksh[n * KPAD + c4 + 2] = kv.z; Ksh[n * KPAD + c4 + 3] = kv.w;
        float4 vv = *(const float4*)(vbase + (long)n * DMOD + c4);
        *(float4*)(Vsh + n * 64 + c4) = vv;
    }
    __syncthreads();

    const int qa = blockIdx.x * 16 + 2 * w;
    const int qb = qa + 1;
    if (qa < NQ) {
        __half* pbA = pbufh + (w * 2 + 0) * NK;
        __half* pbB = pbufh + (w * 2 + 1) * NK;

        const float* qrowA = g_qsig + (long)(b * NQ + qa) * DMOD + h * DK;
        const float* qrowB = g_qsig + (long)(b * NQ + qb) * DMOD + h * DK;
        float qa0 = qrowA[lane], qa1 = qrowA[lane + 32];
        float qb0 = qrowB[lane], qb1 = qrowB[lane + 32];
        float qha0 = 0.5f*qa0, qha1 = 0.5f*qa1, qhb0 = 0.5f*qb0, qhb1 = 0.5f*qb1;

        // ---- Pass 1: scores. Lane owns k = lane + 32*i (7 slots). ----
        float sa[7], sb[7];
        int kb[7];
#pragma unroll
        for (int i = 0; i < 7; i++) { sa[i]=0.f; sb[i]=0.f; kb[i]=(i*32+lane)*KPAD; }
#pragma unroll 4
        for (int d = 0; d < 32; d++) {
            float qaL = __shfl_sync(0xffffffffu, qa0, d);
            float qbL = __shfl_sync(0xffffffffu, qb0, d);
#pragma unroll
            for (int i = 0; i < 7; i++) {
                float kv = Ksh[kb[i] + d];   // OOB rows land in Vsh: defined, masked
                sa[i] = fmaf(qaL, kv, sa[i]);
                sb[i] = fmaf(qbL, kv, sb[i]);
            }
        }
#pragma unroll 4
        for (int d = 0; d < 32; d++) {
            float qaH = __shfl_sync(0xffffffffu, qa1, d);
            float qbH = __shfl_sync(0xffffffffu, qb1, d);
#pragma unroll
            for (int i = 0; i < 7; i++) {
                float kv = Ksh[kb[i] + 32 + d];
                sa[i] = fmaf(qaH, kv, sa[i]);
                sb[i] = fmaf(qbH, kv, sb[i]);
            }
        }

        const float* scrA = scale + (long)(h * NQ + qa) * NK;
        const float* scrB = scale + (long)(h * NQ + qb) * NK;
        float mxa = -1e30f, mxb = -1e30f;
#pragma unroll
        for (int i = 0; i < 7; i++) {
            int k = i * 32 + lane;
            if (k < NK) {
                sa[i] *= scrA[k]; mxa = fmaxf(mxa, sa[i]);
                sb[i] *= scrB[k]; mxb = fmaxf(mxb, sb[i]);
            }
        }
#pragma unroll
        for (int o = 16; o; o >>= 1) {
            mxa = fmaxf(mxa, __shfl_xor_sync(0xffffffffu, mxa, o));
            mxb = fmaxf(mxb, __shfl_xor_sync(0xffffffffu, mxb, o));
        }

        float suma = 0.f, sumb = 0.f;
#pragma unroll
        for (int i = 0; i < 7; i++) {
            int k = i * 32 + lane;
            if (k < NK) {
                float pa = __expf(sa[i] - mxa);
                float pb_ = __expf(sb[i] - mxb);
                pbA[k] = __float2half(0.5f * pa);
                pbB[k] = __float2half(0.5f * pb_);
                suma += pa; sumb += pb_;
            }
        }
#pragma unroll
        for (int o = 16; o; o >>= 1) {
            suma += __shfl_xor_sync(0xffffffffu, suma, o);
            sumb += __shfl_xor_sync(0xffffffffu, sumb, o);
        }
        float rdena = __fdividef(1.f, suma);
        float rdenb = __fdividef(1.f, sumb);
        __syncwarp();

        // ---- Pass 2: gated accumulation, f32 tanh. Lane owns d, d+32. ----
        float aa0 = 0.f, aa1 = 0.f, ab0 = 0.f, ab1 = 0.f;
#pragma unroll 4
        for (int k = 0; k < NK; k++) {
            float hpa = __half2float(pbA[k]);
            float hpb = __half2float(pbB[k]);
            float k0 = Ksh[k * KPAD + lane];
            float k1 = Ksh[k * KPAD + lane + 32];
            float v0 = Vsh[k * 64 + lane];
            float v1 = Vsh[k * 64 + lane + 32];
            float t;
            t = tanhap(qha0 * k0); aa0 = fmaf(fmaf(hpa, t, hpa), v0, aa0);
            t = tanhap(qha1 * k1); aa1 = fmaf(fmaf(hpa, t, hpa), v1, aa1);
            t = tanhap(qhb0 * k0); ab0 = fmaf(fmaf(hpb, t, hpb), v0, ab0);
            t = tanhap(qhb1 * k1); ab1 = fmaf(fmaf(hpb, t, hpb), v1, ab1);
        }

        // epilogue: normalize + bf16 hi/lo split write (out-GEMM operand)
        const long ra = (long)(b * NQ + qa) * DMOD + h * DK;
        const long rb = (long)(b * NQ + qb) * DMOD + h * DK;
        float o;
        __nv_bfloat16 hi;
        o = aa0 * rdena; hi = __float2bfloat16(o);
        g_imghi[ra + lane] = hi;      g_imglo[ra + lane]      = __float2bfloat16(o - __bfloat162float(hi));
        o = aa1 * rdena; hi = __float2bfloat16(o);
        g_imghi[ra + lane + 32] = hi; g_imglo[ra + lane + 32] = __float2bfloat16(o - __bfloat162float(hi));
        o = ab0 * rdenb; hi = __float2bfloat16(o);
        g_imghi[rb + lane] = hi;      g_imglo[rb + lane]      = __float2bfloat16(o - __bfloat162float(hi));
        o = ab1 * rdenb; hi = __float2bfloat16(o);
        g_imghi[rb + lane + 32] = hi; g_imglo[rb + lane + 32] = __float2bfloat16(o - __bfloat162float(hi));
    }
}

// ---------------------------------------------------------------------------
extern "C" void kernel_launch(void* const* d_in, const int* in_sizes, int n_in,
                              void* d_out, int out_size)
{
    const float* queries = (const float*)d_in[0];
    const float* keys    = (const float*)d_in[1];
    const float* values  = (const float*)d_in[2];
    const float* Wq      = (const float*)d_in[3];
    const float* bq      = (const float*)d_in[4];
    const float* Wk      = (const float*)d_in[5];
    const float* bk      = (const float*)d_in[6];
    const float* Wv      = (const float*)d_in[7];
    const float* bv      = (const float*)d_in[8];
    const float* Wo      = (const float*)d_in[9];
    const float* bo      = (const float*)d_in[10];
    const float* scale   = (const float*)d_in[11];
    float* out = (float*)d_out;

    float* qsig; cudaGetSymbolAddress((void**)&qsig, g_qsig);
    float* kp;   cudaGetSymbolAddress((void**)&kp,   g_kp);
    float* vp;   cudaGetSymbolAddress((void**)&vp,   g_vp);
    __nv_bfloat16* xhi;   cudaGetSymbolAddress((void**)&xhi,   g_xhi);
    __nv_bfloat16* xlo;   cudaGetSymbolAddress((void**)&xlo,   g_xlo);
    __nv_bfloat16* whi;   cudaGetSymbolAddress((void**)&whi,   g_whi);
    __nv_bfloat16* wlo;   cudaGetSymbolAddress((void**)&wlo,   g_wlo);
    __nv_bfloat16* imghi; cudaGetSymbolAddress((void**)&imghi, g_imghi);
    __nv_bfloat16* imglo; cudaGetSymbolAddress((void**)&imglo, g_imglo);

    const int smem_attn = (NK * KPAD + NK * 64) * (int)sizeof(float)
                        + 16 * NK * (int)sizeof(__half);
    cudaFuncSetAttribute(attn_kernel, cudaFuncAttributeMaxDynamicSharedMemorySize, smem_attn);

    // 1) split-bf16 conversion of inputs + weights
    dim3 gc((MROWS * DMOD / 8 + 255) / 256, 7);
    convert7_kernel<<<gc, 256>>>(queries, keys, values, Wq, Wk, Wv, Wo);

    // 2) fused Q/K/V projections on tensor cores
    dim3 gg(DMOD / 64, 3, (MROWS + 63) / 64);
    mma_gemm_kernel<0><<<gg, 256>>>(xhi, xlo, whi, wlo,
                                    bq, bk, bv, qsig, kp, vp);

    // 3) attention core (writes bf16 hi/lo img directly)
    dim3 g2((NQ + 15) / 16, BB * NH);
    attn_kernel<<<g2, 256, smem_attn>>>(scale);

    // 4) out-projection + gate on tensor cores
    dim3 g3(DMOD / 64, 1, (MROWS + 63) / 64);
    mma_gemm_kernel<1><<<g3, 256>>>(imghi, imglo, whi + 3L * DMOD * DMOD, wlo + 3L * DMOD * DMOD,
                                    bo, bo, bo, out, out, out);
}